// round 4
// baseline (speedup 1.0000x reference)
#include <cuda_runtime.h>
#include <math.h>

// Problem constants
#define BN   32768
#define DN   512
#define EN   16
#define TK   4
#define TT   3
#define H1N  16
#define H2N  8
#define ON   16

// Tiling
#define ROWS     64     // rows per CTA
#define KC       32     // K chunk
#define NTHREADS 512
#define NCOLS    320    // 256 (h1) + 48 (logits) + 16 zero pad

// Shared memory float offsets (single dynamic allocation, phases alias)
#define XS_OFF   0        // 64*33   = 2112   (GEMM phase)
#define WS_OFF   2112     // 32*320  = 10240  (GEMM phase)  -> GEMM region ends at 12352
#define H1_OFF   0        // 64*273  = 17472  (epilogue, aliases GEMM region)
#define LG_OFF   17472    // 64*49   = 3136
#define B1_OFF   20608    // 256
#define W2_OFF   20864    // 16*130  = 2080
#define W3_OFF   22944    // 16*130  = 2080
#define B2_OFF   25024    // 16*9    = 144
#define B3_OFF   25168    // 16*17   = 272
#define BG_OFF   25440    // 48
#define IMP_OFF  25488    // 48
#define LOAD_OFF 25536    // 48
#define LSE_OFF  25584    // 64
#define SMEM_FLOATS 25648 // 102592 bytes

__device__ float g_imp[TT * EN];
__device__ float g_load[TT * EN];
__device__ float g_rz;

__device__ __forceinline__ unsigned long long bcast2(float v) {
    unsigned long long r;
    unsigned u = __float_as_uint(v);
    asm("mov.b64 %0, {%1, %1};" : "=l"(r) : "r"(u));
    return r;
}

__device__ __forceinline__ void fma2(unsigned long long& d, unsigned long long a,
                                     unsigned long long b) {
    asm("fma.rn.f32x2 %0, %1, %2, %0;" : "+l"(d) : "l"(a), "l"(b));
}

__device__ __forceinline__ void unpack2(unsigned long long v, float& lo, float& hi) {
    asm("mov.b64 {%0, %1}, %2;" : "=f"(lo), "=f"(hi) : "l"(v));
}

__global__ void moe_init_kernel() {
    int i = threadIdx.x;
    if (i < TT * EN) { g_imp[i] = 0.f; g_load[i] = 0.f; }
    if (i == 0) g_rz = 0.f;
}

extern __shared__ float sm[];

__global__ __launch_bounds__(NTHREADS, 1)
void moe_main_kernel(const float* __restrict__ x,
                     const float* __restrict__ wgates,
                     const float* __restrict__ bgates,
                     const float* __restrict__ W1,
                     const float* __restrict__ b1,
                     const float* __restrict__ W2,
                     const float* __restrict__ b2,
                     const float* __restrict__ W3,
                     const float* __restrict__ b3,
                     float* __restrict__ out) {
    const int tid  = threadIdx.x;
    const int row0 = blockIdx.x * ROWS;
    const int tx   = tid & 31;   // column group
    const int ty   = tid >> 5;   // row group (0..15)
    const int rbase = ty * 4;

    // ---- Stage small persistent weights into padded (conflict-free) smem ----
    for (int i = tid; i < 256; i += NTHREADS) sm[B1_OFF + i] = b1[i];
    for (int i = tid; i < 2048; i += NTHREADS) {
        sm[W2_OFF + (i >> 7) * 130 + (i & 127)] = W2[i];
        sm[W3_OFF + (i >> 7) * 130 + (i & 127)] = W3[i];
    }
    for (int i = tid; i < 128; i += NTHREADS) sm[B2_OFF + (i >> 3) * 9 + (i & 7)] = b2[i];
    for (int i = tid; i < 256; i += NTHREADS) sm[B3_OFF + (i >> 4) * 17 + (i & 15)] = b3[i];
    if (tid < 48) {
        sm[BG_OFF + tid] = bgates[tid];
        sm[IMP_OFF + tid] = 0.f;
        sm[LOAD_OFF + tid] = 0.f;
    }

    // ---- GEMM accumulators: 4 rows x 5 f32x2 column pairs ----
    unsigned long long acc[4][5];
#pragma unroll
    for (int i = 0; i < 4; i++)
#pragma unroll
        for (int j = 0; j < 5; j++) acc[i][j] = 0ull;

    // online logsumexp state (threads 0..63, one row each)
    float lm = -INFINITY, ls = 0.f;

    for (int kc = 0; kc < DN / KC; ++kc) {
        // stage x tile: xs[r][kk], row stride 33 (conflict-free row scans)
        {
            int r = tid >> 3, q = tid & 7;
            float4 v = *(const float4*)(x + (size_t)(row0 + r) * DN + kc * KC + q * 4);
            float* xp = &sm[XS_OFF + r * 33 + q * 4];
            xp[0] = v.x; xp[1] = v.y; xp[2] = v.z; xp[3] = v.w;
        }
        // stage W tile: ws[kk][n], n<256 -> W1[e=n/16, d, h=n%16]; n<304 -> gates
#pragma unroll
        for (int it = 0; it < (KC * NCOLS) / NTHREADS; ++it) {
            int idx = tid + it * NTHREADS;
            int kk = idx / NCOLS;
            int n = idx - kk * NCOLS;
            int d = kc * KC + kk;
            float w;
            if (n < 256) {
                w = W1[(n >> 4) * (DN * H1N) + d * 16 + (n & 15)];
            } else if (n < 304) {
                int m = n - 256;
                w = wgates[(m >> 4) * (DN * EN) + d * 16 + (m & 15)];
            } else {
                w = 0.f;
            }
            sm[WS_OFF + kk * NCOLS + n] = w;
        }
        __syncthreads();

        // logsumexp update (row-per-thread over this chunk)
        if (tid < ROWS) {
            const float* xr = &sm[XS_OFF + tid * 33];
            float cm = xr[0];
#pragma unroll
            for (int kk = 1; kk < KC; ++kk) cm = fmaxf(cm, xr[kk]);
            float nm = fmaxf(lm, cm);
            ls *= __expf(lm - nm);
            float add = 0.f;
#pragma unroll
            for (int kk = 0; kk < KC; ++kk) add += __expf(xr[kk] - nm);
            ls += add;
            lm = nm;
        }

        // f32x2 outer-product GEMM
#pragma unroll 4
        for (int kk = 0; kk < KC; ++kk) {
            unsigned long long a2[4];
#pragma unroll
            for (int i = 0; i < 4; i++) a2[i] = bcast2(sm[XS_OFF + (rbase + i) * 33 + kk]);
#pragma unroll
            for (int j = 0; j < 5; j++) {
                unsigned long long bb =
                    *(const unsigned long long*)&sm[WS_OFF + kk * NCOLS + 2 * (tx + 32 * j)];
#pragma unroll
                for (int i = 0; i < 4; i++) fma2(acc[i][j], a2[i], bb);
            }
        }
        __syncthreads();
    }

    // ---- write accumulators into padded epilogue smem (h1 with bias+relu, logits) ----
#pragma unroll
    for (int j = 0; j < 5; j++) {
        int c = 2 * (tx + 32 * j);
#pragma unroll
        for (int i = 0; i < 4; i++) {
            int row = rbase + i;
            float vx, vy;
            unpack2(acc[i][j], vx, vy);
            if (c < 256) {
                int e = c >> 4, h = c & 15;  // c even -> h<=14, pair stays in-expert
                sm[H1_OFF + row * 273 + e * 17 + h]     = fmaxf(vx + sm[B1_OFF + c], 0.f);
                sm[H1_OFF + row * 273 + e * 17 + h + 1] = fmaxf(vy + sm[B1_OFF + c + 1], 0.f);
            } else if (c < 304) {
                int m = c - 256;
                sm[LG_OFF + row * 49 + m]     = vx + sm[BG_OFF + m];
                sm[LG_OFF + row * 49 + m + 1] = vy + sm[BG_OFF + m + 1];
            }
        }
    }
    if (tid < ROWS) sm[LSE_OFF + tid] = lm + __logf(ls);
    __syncthreads();

    if (tid == 0) {
        float s = 0.f;
        for (int r = 0; r < ROWS; r++) s += sm[LSE_OFF + r];
        atomicAdd(&g_rz, s);
    }

    // ---- gating + sparse expert layers 2/3: one thread per (task,row) ----
    if (tid < ROWS * TT) {
        int t = tid / ROWS;
        int row = tid - t * ROWS;
        float l[16];
#pragma unroll
        for (int e = 0; e < 16; e++) l[e] = sm[LG_OFF + row * 49 + t * 16 + e];
        int sel[4];
        float sv[4];
#pragma unroll
        for (int k = 0; k < 4; k++) {
            float best = -INFINITY;
            int bi = 0;
#pragma unroll
            for (int e = 0; e < 16; e++)
                if (l[e] > best) { best = l[e]; bi = e; }
            sv[k] = best;
            sel[k] = bi;
            l[bi] = -INFINITY;
        }
        float m = sv[0];
        float g[4], ssum = 0.f;
#pragma unroll
        for (int k = 0; k < 4; k++) { g[k] = __expf(sv[k] - m); ssum += g[k]; }
        float inv = 1.f / ssum;

        float y[16];
#pragma unroll
        for (int o = 0; o < 16; o++) y[o] = 0.f;

#pragma unroll
        for (int k = 0; k < 4; k++) {
            int e = sel[k];
            float gk = g[k] * inv;
            float h[16];
#pragma unroll
            for (int i = 0; i < 16; i++) h[i] = sm[H1_OFF + row * 273 + e * 17 + i];
            float h2v[8];
#pragma unroll
            for (int j = 0; j < 8; j++) {
                float a = sm[B2_OFF + e * 9 + j];
#pragma unroll
                for (int i = 0; i < 16; i++) a += h[i] * sm[W2_OFF + e * 130 + i * 8 + j];
                h2v[j] = fmaxf(a, 0.f);
            }
#pragma unroll
            for (int o = 0; o < 16; o++) {
                float a = sm[B3_OFF + e * 17 + o];
#pragma unroll
                for (int j = 0; j < 8; j++) a += h2v[j] * sm[W3_OFF + e * 130 + j * 16 + o];
                y[o] += gk * fmaxf(a, 0.f);
            }
            atomicAdd(&sm[IMP_OFF + t * 16 + e], gk);
            atomicAdd(&sm[LOAD_OFF + t * 16 + e], 1.f);
        }
        float* yo = out + (size_t)t * BN * ON + (size_t)(row0 + row) * ON;
#pragma unroll
        for (int o = 0; o < 16; o++) yo[o] = y[o];
    }
    __syncthreads();

    // flush per-CTA loss partials
    if (tid < 48) atomicAdd(&g_imp[tid], sm[IMP_OFF + tid]);
    else if (tid < 96) atomicAdd(&g_load[tid - 48], sm[LOAD_OFF + tid - 48]);
}

__global__ void moe_finalize_kernel(float* __restrict__ out, int out_size) {
    if (threadIdx.x != 0 || blockIdx.x != 0) return;
    float lb = 0.f;
    for (int t = 0; t < TT; t++) {
        float imp[16], ld[16];
        float si = 0.f, sl = 0.f, sil = 0.f;
        for (int e = 0; e < 16; e++) {
            imp[e] = g_imp[t * 16 + e];
            ld[e]  = g_load[t * 16 + e];
            si += imp[e]; sl += ld[e]; sil += imp[e] * ld[e];
        }
        float mi = si / 16.f, ml = sl / 16.f;
        float vi = 0.f, vl = 0.f;
        for (int e = 0; e < 16; e++) {
            float di = imp[e] - mi, dl = ld[e] - ml;
            vi += di * di; vl += dl * dl;
        }
        vi /= 15.f;  // ddof=1
        vl /= 15.f;
        float cvi = vi / (mi * mi + 1e-10f);
        float cvl = vl / (ml * ml + 1e-10f);
        lb += 0.01f * (cvi + cvl) + 0.01f * 16.f * sil / (float)BN;
    }
    size_t base = (size_t)TT * BN * ON;
    if (out_size > (int)base)     out[base]     = lb;
    if (out_size > (int)base + 1) out[base + 1] = 3.f * 0.001f * g_rz / (float)BN;
}

extern "C" void kernel_launch(void* const* d_in, const int* in_sizes, int n_in,
                              void* d_out, int out_size) {
    const float* x      = (const float*)d_in[0];
    const float* wgates = (const float*)d_in[1];
    const float* bgates = (const float*)d_in[2];
    const float* W1     = (const float*)d_in[3];
    const float* b1     = (const float*)d_in[4];
    const float* W2     = (const float*)d_in[5];
    const float* b2     = (const float*)d_in[6];
    const float* W3     = (const float*)d_in[7];
    const float* b3     = (const float*)d_in[8];
    float* out = (float*)d_out;

    cudaFuncSetAttribute(moe_main_kernel, cudaFuncAttributeMaxDynamicSharedMemorySize,
                         SMEM_FLOATS * sizeof(float));

    moe_init_kernel<<<1, 64>>>();
    moe_main_kernel<<<BN / ROWS, NTHREADS, SMEM_FLOATS * sizeof(float)>>>(
        x, wgates, bgates, W1, b1, W2, b2, W3, b3, out);
    moe_finalize_kernel<<<1, 32>>>(out, out_size);
}

// round 5
// speedup vs baseline: 1.0026x; 1.0026x over previous
#include <cuda_runtime.h>
#include <math.h>

// Problem constants
#define BN   32768
#define DN   512
#define EN   16
#define TK   4
#define TT   3
#define H1N  16
#define H2N  8
#define ON   16

// Tiling
#define ROWS     64     // rows per CTA
#define KC       32     // K chunk
#define NTHREADS 512
#define NCOLS    320    // 256 (h1) + 48 (logits) + 16 zero pad

// Shared memory float offsets (single dynamic allocation, phases alias)
#define XS_OFF   0        // 64*33   = 2112   (GEMM phase)
#define WS_OFF   2112     // 32*320  = 10240  (GEMM phase)  -> GEMM region ends at 12352
#define H1_OFF   0        // 64*273  = 17472  (epilogue, aliases GEMM region)
#define LG_OFF   17472    // 64*49   = 3136
#define B1_OFF   20608    // 256
#define W2_OFF   20864    // 16*130  = 2080
#define W3_OFF   22944    // 16*130  = 2080
#define B2_OFF   25024    // 16*9    = 144
#define B3_OFF   25168    // 16*17   = 272
#define BG_OFF   25440    // 48
#define IMP_OFF  25488    // 48
#define LOAD_OFF 25536    // 48
#define LSE_OFF  25584    // 64
#define SMEM_FLOATS 25648 // 102592 bytes

__device__ float g_imp[TT * EN];
__device__ float g_load[TT * EN];
__device__ float g_rz;

__device__ __forceinline__ unsigned long long bcast2(float v) {
    unsigned long long r;
    unsigned u = __float_as_uint(v);
    asm("mov.b64 %0, {%1, %1};" : "=l"(r) : "r"(u));
    return r;
}

__device__ __forceinline__ void fma2(unsigned long long& d, unsigned long long a,
                                     unsigned long long b) {
    asm("fma.rn.f32x2 %0, %1, %2, %0;" : "+l"(d) : "l"(a), "l"(b));
}

__device__ __forceinline__ void unpack2(unsigned long long v, float& lo, float& hi) {
    asm("mov.b64 {%0, %1}, %2;" : "=f"(lo), "=f"(hi) : "l"(v));
}

__global__ void moe_init_kernel() {
    int i = threadIdx.x;
    if (i < TT * EN) { g_imp[i] = 0.f; g_load[i] = 0.f; }
    if (i == 0) g_rz = 0.f;
}

extern __shared__ float sm[];

__global__ __launch_bounds__(NTHREADS, 1)
void moe_main_kernel(const float* __restrict__ x,
                     const float* __restrict__ wgates,
                     const float* __restrict__ bgates,
                     const float* __restrict__ W1,
                     const float* __restrict__ b1,
                     const float* __restrict__ W2,
                     const float* __restrict__ b2,
                     const float* __restrict__ W3,
                     const float* __restrict__ b3,
                     float* __restrict__ out) {
    const int tid  = threadIdx.x;
    const int row0 = blockIdx.x * ROWS;
    const int tx   = tid & 31;   // column group
    const int ty   = tid >> 5;   // row group (0..15)
    const int rbase = ty * 4;

    // ---- Stage small persistent weights into padded (conflict-free) smem ----
    for (int i = tid; i < 256; i += NTHREADS) sm[B1_OFF + i] = b1[i];
    for (int i = tid; i < 2048; i += NTHREADS) {
        sm[W2_OFF + (i >> 7) * 130 + (i & 127)] = W2[i];
        sm[W3_OFF + (i >> 7) * 130 + (i & 127)] = W3[i];
    }
    for (int i = tid; i < 128; i += NTHREADS) sm[B2_OFF + (i >> 3) * 9 + (i & 7)] = b2[i];
    for (int i = tid; i < 256; i += NTHREADS) sm[B3_OFF + (i >> 4) * 17 + (i & 15)] = b3[i];
    if (tid < 48) {
        sm[BG_OFF + tid] = bgates[tid];
        sm[IMP_OFF + tid] = 0.f;
        sm[LOAD_OFF + tid] = 0.f;
    }

    // ---- GEMM accumulators: 4 rows x 5 f32x2 column pairs ----
    unsigned long long acc[4][5];
#pragma unroll
    for (int i = 0; i < 4; i++)
#pragma unroll
        for (int j = 0; j < 5; j++) acc[i][j] = 0ull;

    // online logsumexp state (threads 0..63, one row each)
    float lm = -INFINITY, ls = 0.f;

    for (int kc = 0; kc < DN / KC; ++kc) {
        // stage x tile: xs[r][kk], row stride 33 (conflict-free row scans)
        {
            int r = tid >> 3, q = tid & 7;
            float4 v = *(const float4*)(x + (size_t)(row0 + r) * DN + kc * KC + q * 4);
            float* xp = &sm[XS_OFF + r * 33 + q * 4];
            xp[0] = v.x; xp[1] = v.y; xp[2] = v.z; xp[3] = v.w;
        }
        // stage W tile: ws[kk][n], n<256 -> W1[e=n/16, d, h=n%16]; n<304 -> gates
#pragma unroll
        for (int it = 0; it < (KC * NCOLS) / NTHREADS; ++it) {
            int idx = tid + it * NTHREADS;
            int kk = idx / NCOLS;
            int n = idx - kk * NCOLS;
            int d = kc * KC + kk;
            float w;
            if (n < 256) {
                w = W1[(n >> 4) * (DN * H1N) + d * 16 + (n & 15)];
            } else if (n < 304) {
                int m = n - 256;
                w = wgates[(m >> 4) * (DN * EN) + d * 16 + (m & 15)];
            } else {
                w = 0.f;
            }
            sm[WS_OFF + kk * NCOLS + n] = w;
        }
        __syncthreads();

        // logsumexp update (row-per-thread over this chunk)
        if (tid < ROWS) {
            const float* xr = &sm[XS_OFF + tid * 33];
            float cm = xr[0];
#pragma unroll
            for (int kk = 1; kk < KC; ++kk) cm = fmaxf(cm, xr[kk]);
            float nm = fmaxf(lm, cm);
            ls *= __expf(lm - nm);
            float add = 0.f;
#pragma unroll
            for (int kk = 0; kk < KC; ++kk) add += __expf(xr[kk] - nm);
            ls += add;
            lm = nm;
        }

        // f32x2 outer-product GEMM
#pragma unroll 4
        for (int kk = 0; kk < KC; ++kk) {
            unsigned long long a2[4];
#pragma unroll
            for (int i = 0; i < 4; i++) a2[i] = bcast2(sm[XS_OFF + (rbase + i) * 33 + kk]);
#pragma unroll
            for (int j = 0; j < 5; j++) {
                unsigned long long bb =
                    *(const unsigned long long*)&sm[WS_OFF + kk * NCOLS + 2 * (tx + 32 * j)];
#pragma unroll
                for (int i = 0; i < 4; i++) fma2(acc[i][j], a2[i], bb);
            }
        }
        __syncthreads();
    }

    // ---- write accumulators into padded epilogue smem (h1 with bias+relu, logits) ----
#pragma unroll
    for (int j = 0; j < 5; j++) {
        int c = 2 * (tx + 32 * j);
#pragma unroll
        for (int i = 0; i < 4; i++) {
            int row = rbase + i;
            float vx, vy;
            unpack2(acc[i][j], vx, vy);
            if (c < 256) {
                int e = c >> 4, h = c & 15;  // c even -> h<=14, pair stays in-expert
                sm[H1_OFF + row * 273 + e * 17 + h]     = fmaxf(vx + sm[B1_OFF + c], 0.f);
                sm[H1_OFF + row * 273 + e * 17 + h + 1] = fmaxf(vy + sm[B1_OFF + c + 1], 0.f);
            } else if (c < 304) {
                int m = c - 256;
                sm[LG_OFF + row * 49 + m]     = vx + sm[BG_OFF + m];
                sm[LG_OFF + row * 49 + m + 1] = vy + sm[BG_OFF + m + 1];
            }
        }
    }
    if (tid < ROWS) sm[LSE_OFF + tid] = lm + __logf(ls);
    __syncthreads();

    if (tid == 0) {
        float s = 0.f;
        for (int r = 0; r < ROWS; r++) s += sm[LSE_OFF + r];
        atomicAdd(&g_rz, s);
    }

    // ---- gating + sparse expert layers 2/3: one thread per (task,row) ----
    if (tid < ROWS * TT) {
        int t = tid / ROWS;
        int row = tid - t * ROWS;
        float l[16];
#pragma unroll
        for (int e = 0; e < 16; e++) l[e] = sm[LG_OFF + row * 49 + t * 16 + e];
        int sel[4];
        float sv[4];
#pragma unroll
        for (int k = 0; k < 4; k++) {
            float best = -INFINITY;
            int bi = 0;
#pragma unroll
            for (int e = 0; e < 16; e++)
                if (l[e] > best) { best = l[e]; bi = e; }
            sv[k] = best;
            sel[k] = bi;
            l[bi] = -INFINITY;
        }
        float m = sv[0];
        float g[4], ssum = 0.f;
#pragma unroll
        for (int k = 0; k < 4; k++) { g[k] = __expf(sv[k] - m); ssum += g[k]; }
        float inv = 1.f / ssum;

        float y[16];
#pragma unroll
        for (int o = 0; o < 16; o++) y[o] = 0.f;

#pragma unroll
        for (int k = 0; k < 4; k++) {
            int e = sel[k];
            float gk = g[k] * inv;
            float h[16];
#pragma unroll
            for (int i = 0; i < 16; i++) h[i] = sm[H1_OFF + row * 273 + e * 17 + i];
            float h2v[8];
#pragma unroll
            for (int j = 0; j < 8; j++) {
                float a = sm[B2_OFF + e * 9 + j];
#pragma unroll
                for (int i = 0; i < 16; i++) a += h[i] * sm[W2_OFF + e * 130 + i * 8 + j];
                h2v[j] = fmaxf(a, 0.f);
            }
#pragma unroll
            for (int o = 0; o < 16; o++) {
                float a = sm[B3_OFF + e * 17 + o];
#pragma unroll
                for (int j = 0; j < 8; j++) a += h2v[j] * sm[W3_OFF + e * 130 + j * 16 + o];
                y[o] += gk * fmaxf(a, 0.f);
            }
            atomicAdd(&sm[IMP_OFF + t * 16 + e], gk);
            atomicAdd(&sm[LOAD_OFF + t * 16 + e], 1.f);
        }
        float* yo = out + (size_t)t * BN * ON + (size_t)(row0 + row) * ON;
#pragma unroll
        for (int o = 0; o < 16; o++) yo[o] = y[o];
    }
    __syncthreads();

    // flush per-CTA loss partials
    if (tid < 48) atomicAdd(&g_imp[tid], sm[IMP_OFF + tid]);
    else if (tid < 96) atomicAdd(&g_load[tid - 48], sm[LOAD_OFF + tid - 48]);
}

__global__ void moe_finalize_kernel(float* __restrict__ out, int out_size) {
    if (threadIdx.x != 0 || blockIdx.x != 0) return;
    float lb = 0.f;
    for (int t = 0; t < TT; t++) {
        float imp[16], ld[16];
        float si = 0.f, sl = 0.f, sil = 0.f;
        for (int e = 0; e < 16; e++) {
            imp[e] = g_imp[t * 16 + e];
            ld[e]  = g_load[t * 16 + e];
            si += imp[e]; sl += ld[e]; sil += imp[e] * ld[e];
        }
        float mi = si / 16.f, ml = sl / 16.f;
        float vi = 0.f, vl = 0.f;
        for (int e = 0; e < 16; e++) {
            float di = imp[e] - mi, dl = ld[e] - ml;
            vi += di * di; vl += dl * dl;
        }
        vi /= 15.f;  // ddof=1
        vl /= 15.f;
        float cvi = vi / (mi * mi + 1e-10f);
        float cvl = vl / (ml * ml + 1e-10f);
        lb += 0.01f * (cvi + cvl) + 0.01f * 16.f * sil / (float)BN;
    }
    size_t base = (size_t)TT * BN * ON;
    if (out_size > (int)base)     out[base]     = lb;
    if (out_size > (int)base + 1) out[base + 1] = 3.f * 0.001f * g_rz / (float)BN;
}

extern "C" void kernel_launch(void* const* d_in, const int* in_sizes, int n_in,
                              void* d_out, int out_size) {
    const float* x      = (const float*)d_in[0];
    const float* wgates = (const float*)d_in[1];
    const float* bgates = (const float*)d_in[2];
    const float* W1     = (const float*)d_in[3];
    const float* b1     = (const float*)d_in[4];
    const float* W2     = (const float*)d_in[5];
    const float* b2     = (const float*)d_in[6];
    const float* W3     = (const float*)d_in[7];
    const float* b3     = (const float*)d_in[8];
    float* out = (float*)d_out;

    cudaFuncSetAttribute(moe_main_kernel, cudaFuncAttributeMaxDynamicSharedMemorySize,
                         SMEM_FLOATS * sizeof(float));

    moe_init_kernel<<<1, 64>>>();
    moe_main_kernel<<<BN / ROWS, NTHREADS, SMEM_FLOATS * sizeof(float)>>>(
        x, wgates, bgates, W1, b1, W2, b2, W3, b3, out);
    moe_finalize_kernel<<<1, 32>>>(out, out_size);
}

// round 8
// speedup vs baseline: 3.1263x; 3.1181x over previous
#include <cuda_runtime.h>
#include <cuda_bf16.h>
#include <stdint.h>
#include <math.h>

#define BN 32768
#define DN 512
#define EN 16
#define TT 3
#define ON 16
#define MROWS 128
#define NTH 512
#define NCHUNK 16
#define KC 32
#define CHB 52480           // B chunk bytes: 2*256*80 + 3*48*80
#define ATERM 10240         // A per-term bytes (128 rows * 80)
#define ABUF 30720          // A per-buffer (3 terms)
#define BBASE 61440         // B region start (after 2 A buffers)
// float offsets
#define H1_F 0              // 128*273 floats (aliases GEMM buffers)
#define LG_F 34944          // 128*49
#define B1T 41600
#define BGT 41856
#define W2T 41904
#define W3T 43984
#define B2T 46064
#define B3T 46208
#define IMPT 46480
#define LDT 46528
#define LSET 46576
#define SMEM_BYTES 186816

__device__ __align__(16) unsigned char g_wimg[NCHUNK * CHB];
__device__ float g_imp[TT * EN];
__device__ float g_load[TT * EN];
__device__ float g_rz;

__device__ __forceinline__ uint32_t smem_u32(const void* p) {
    uint32_t a;
    asm("{ .reg .u64 t; cvta.to.shared.u64 t, %1; cvt.u32.u64 %0, t; }" : "=r"(a) : "l"(p));
    return a;
}
__device__ __forceinline__ void ldsm4(uint32_t* r, uint32_t a) {
    asm volatile("ldmatrix.sync.aligned.m8n8.x4.shared.b16 {%0,%1,%2,%3}, [%4];"
                 : "=r"(r[0]), "=r"(r[1]), "=r"(r[2]), "=r"(r[3]) : "r"(a));
}
__device__ __forceinline__ void ldsm2(uint32_t* r, uint32_t a) {
    asm volatile("ldmatrix.sync.aligned.m8n8.x2.shared.b16 {%0,%1}, [%2];"
                 : "=r"(r[0]), "=r"(r[1]) : "r"(a));
}
__device__ __forceinline__ void mmab(float* c, const uint32_t* a, const uint32_t* b) {
    asm volatile("mma.sync.aligned.m16n8k16.row.col.f32.bf16.bf16.f32 "
                 "{%0,%1,%2,%3},{%4,%5,%6,%7},{%8,%9},{%0,%1,%2,%3};"
                 : "+f"(c[0]), "+f"(c[1]), "+f"(c[2]), "+f"(c[3])
                 : "r"(a[0]), "r"(a[1]), "r"(a[2]), "r"(a[3]), "r"(b[0]), "r"(b[1]));
}
__device__ __forceinline__ void cpa16(uint32_t d, const void* s) {
    asm volatile("cp.async.cg.shared.global [%0], [%1], 16;" :: "r"(d), "l"(s) : "memory");
}

// ---------- prepass: pad+split weights into per-chunk image ----------
__global__ void moe_prep(const float* __restrict__ W1, const float* __restrict__ wg) {
    if (blockIdx.x == 0) {
        int i = threadIdx.x;
        if (i < TT * EN) { g_imp[i] = 0.f; g_load[i] = 0.f; }
        if (i == 0) g_rz = 0.f;
    }
    int idx = blockIdx.x * blockDim.x + threadIdx.x;
    if (idx >= NCHUNK * 304 * KC) return;
    int c = idx / (304 * KC);
    int r = idx - c * (304 * KC);
    int n = r >> 5, k = r & 31, d = c * KC + k;
    unsigned char* base = g_wimg + (size_t)c * CHB;
    float w;
    if (n < 256) w = W1[(n >> 4) * (DN * 16) + d * 16 + (n & 15)];
    else { int m = n - 256; w = wg[(m >> 4) * (DN * EN) + d * 16 + (m & 15)]; }
    __nv_bfloat16 t0 = __float2bfloat16(w);
    float r1 = w - __bfloat162float(t0);
    __nv_bfloat16 t1 = __float2bfloat16(r1);
    if (n < 256) {
        *(__nv_bfloat16*)(base + n * 80 + 2 * k) = t0;
        *(__nv_bfloat16*)(base + 20480 + n * 80 + 2 * k) = t1;
    } else {
        int gn = n - 256;
        __nv_bfloat16 t2 = __float2bfloat16(r1 - __bfloat162float(t1));
        *(__nv_bfloat16*)(base + 40960 + gn * 80 + 2 * k) = t0;
        *(__nv_bfloat16*)(base + 44800 + gn * 80 + 2 * k) = t1;
        *(__nv_bfloat16*)(base + 48640 + gn * 80 + 2 * k) = t2;
    }
}

// ---------- main ----------
extern __shared__ float sm[];

__global__ __launch_bounds__(NTH, 1)
void moe_mma(const float* __restrict__ x,
             const float* __restrict__ bgates,
             const float* __restrict__ b1,
             const float* __restrict__ W2,
             const float* __restrict__ b2,
             const float* __restrict__ W3,
             const float* __restrict__ b3,
             float* __restrict__ out) {
    const int tid = threadIdx.x;
    const int wid = tid >> 5, l = tid & 31;
    const int mrow = wid & 3, ncol = wid >> 2;
    const int row0 = blockIdx.x * MROWS;
    const uint32_t sb = smem_u32(sm);

    for (int i = tid; i < 256; i += NTH) sm[B1T + i] = b1[i];
    if (tid < 48) { sm[BGT + tid] = bgates[tid]; sm[IMPT + tid] = 0.f; sm[LDT + tid] = 0.f; }
    for (int i = tid; i < 2048; i += NTH) {
        sm[W2T + (i >> 7) * 130 + (i & 127)] = W2[i];
        sm[W3T + (i >> 7) * 130 + (i & 127)] = W3[i];
    }
    for (int i = tid; i < 128; i += NTH) sm[B2T + (i >> 3) * 9 + (i & 7)] = b2[i];
    for (int i = tid; i < 256; i += NTH) sm[B3T + (i >> 4) * 17 + (i & 15)] = b3[i];

    float c[2][10][4];
#pragma unroll
    for (int i = 0; i < 2; i++)
#pragma unroll
        for (int j = 0; j < 10; j++)
#pragma unroll
            for (int q = 0; q < 4; q++) c[i][j][q] = 0.f;

    const uint32_t aoff = (uint32_t)((mrow * 32 + ((l >> 3) & 1) * 8 + (l & 7)) * 80 + (l >> 4) * 16);
    const uint32_t boff = (uint32_t)((l & 7) * 80 + ((l >> 3) & 1) * 16);
    const int srow = tid >> 2, skq = tid & 3;
    const float* xp = x + (size_t)(row0 + srow) * DN + skq * 8;
    const uint32_t stoff = (uint32_t)(srow * 80 + skq * 16);
    float lm = -INFINITY, ls = 0.f;
    float4 xa, xb;

#define STAGE_B(ch_, bq) do {                                                  \
    const unsigned char* s_ = g_wimg + (size_t)(ch_) * CHB;                    \
    uint32_t d_ = sb + BBASE + (bq) * CHB;                                     \
    _Pragma("unroll") for (int j_ = 0; j_ < 7; j_++) {                         \
        uint32_t o_ = (uint32_t)tid * 16 + j_ * 8192;                          \
        if (o_ < CHB) cpa16(d_ + o_, s_ + o_);                                 \
    }                                                                          \
    asm volatile("cp.async.commit_group;" ::: "memory"); } while (0)

#define STAGE_A(bq) do {                                                       \
    float v_[8] = {xa.x, xa.y, xa.z, xa.w, xb.x, xb.y, xb.z, xb.w};            \
    float cm_ = v_[0];                                                         \
    _Pragma("unroll") for (int i_ = 1; i_ < 8; i_++) cm_ = fmaxf(cm_, v_[i_]); \
    float nm_ = fmaxf(lm, cm_);                                                \
    ls *= __expf(lm - nm_);                                                    \
    float ad_ = 0.f;                                                           \
    _Pragma("unroll") for (int i_ = 0; i_ < 8; i_++) ad_ += __expf(v_[i_] - nm_); \
    ls += ad_; lm = nm_;                                                       \
    _Pragma("unroll") for (int t_ = 0; t_ < 3; t_++) {                         \
        uint32_t rr_[4];                                                       \
        _Pragma("unroll") for (int i_ = 0; i_ < 4; i_++) {                     \
            __nv_bfloat16 p0_ = __float2bfloat16(v_[2 * i_]);                  \
            __nv_bfloat16 p1_ = __float2bfloat16(v_[2 * i_ + 1]);              \
            v_[2 * i_]     -= __bfloat162float(p0_);                           \
            v_[2 * i_ + 1] -= __bfloat162float(p1_);                           \
            rr_[i_] = ((uint32_t)__bfloat16_as_ushort(p1_) << 16) |            \
                      (uint32_t)__bfloat16_as_ushort(p0_);                     \
        }                                                                      \
        asm volatile("st.shared.v4.b32 [%0], {%1,%2,%3,%4};"                   \
            :: "r"(sb + (bq) * ABUF + t_ * ATERM + stoff),                     \
               "r"(rr_[0]), "r"(rr_[1]), "r"(rr_[2]), "r"(rr_[3]) : "memory"); \
    } } while (0)

    xa = *(const float4*)xp;
    xb = *(const float4*)(xp + 4);
    STAGE_B(0, 0);
    STAGE_A(0);

    for (int ch = 0; ch < NCHUNK; ++ch) {
        int buf = ch & 1;
        if (ch < NCHUNK - 1) {
            const float* xq = xp + (ch + 1) * KC;
            xa = *(const float4*)xq;
            xb = *(const float4*)(xq + 4);
        }
        asm volatile("cp.async.wait_group 0;" ::: "memory");
        __syncthreads();
        if (ch < NCHUNK - 1) STAGE_B(ch + 1, buf ^ 1);

        {
            uint32_t Ab = sb + buf * ABUF;
            uint32_t Bb = sb + BBASE + buf * CHB;
            if (ncol < 3) {
#pragma unroll
                for (int ks = 0; ks < 2; ++ks) {
                    uint32_t a[2][2][4];
#pragma unroll
                    for (int t = 0; t < 2; t++)
#pragma unroll
                        for (int mt = 0; mt < 2; mt++)
                            ldsm4(a[t][mt], Ab + t * ATERM + aoff + mt * 1280 + ks * 32);
#pragma unroll
                    for (int nt = 0; nt < 10; ++nt) {
                        uint32_t b0[2], b1[2];
                        uint32_t ba = Bb + (uint32_t)((ncol * 80 + nt * 8) * 80) + boff + ks * 32;
                        ldsm2(b0, ba);
                        ldsm2(b1, ba + 20480);
#pragma unroll
                        for (int mt = 0; mt < 2; mt++) {
                            mmab(c[mt][nt], a[0][mt], b0);
                            mmab(c[mt][nt], a[1][mt], b0);
                            mmab(c[mt][nt], a[0][mt], b1);
                        }
                    }
                }
            } else {
#pragma unroll
                for (int ks = 0; ks < 2; ++ks) {
                    uint32_t a[3][2][4];
#pragma unroll
                    for (int t = 0; t < 3; t++)
#pragma unroll
                        for (int mt = 0; mt < 2; mt++)
                            ldsm4(a[t][mt], Ab + t * ATERM + aoff + mt * 1280 + ks * 32);
#pragma unroll
                    for (int nt = 0; nt < 2; ++nt) {
                        uint32_t b0[2], b1[2];
                        uint32_t ba = Bb + (uint32_t)((240 + nt * 8) * 80) + boff + ks * 32;
                        ldsm2(b0, ba);
                        ldsm2(b1, ba + 20480);
#pragma unroll
                        for (int mt = 0; mt < 2; mt++) {
                            mmab(c[mt][nt], a[0][mt], b0);
                            mmab(c[mt][nt], a[1][mt], b0);
                            mmab(c[mt][nt], a[0][mt], b1);
                        }
                    }
#pragma unroll
                    for (int nt = 0; nt < 6; ++nt) {
                        uint32_t b0[2], b1[2], b2[2];
                        uint32_t ba = Bb + 40960u + (uint32_t)(nt * 8 * 80) + boff + ks * 32;
                        ldsm2(b0, ba);
                        ldsm2(b1, ba + 3840);
                        ldsm2(b2, ba + 7680);
#pragma unroll
                        for (int mt = 0; mt < 2; mt++) {
                            float* cc = c[mt][2 + nt];
                            mmab(cc, a[0][mt], b0);
                            mmab(cc, a[0][mt], b1);
                            mmab(cc, a[1][mt], b0);
                            mmab(cc, a[1][mt], b1);
                            mmab(cc, a[0][mt], b2);
                            mmab(cc, a[2][mt], b0);
                        }
                    }
                }
            }
        }
        if (ch < NCHUNK - 1) STAGE_A(buf ^ 1);
    }
    __syncthreads();

    // ---- C writeback: bias + relu into padded epilogue smem ----
    {
        int r4 = l >> 2, c2 = 2 * (l & 3);
        if (ncol < 3) {
#pragma unroll
            for (int mt = 0; mt < 2; mt++)
#pragma unroll
                for (int nt = 0; nt < 10; nt++) {
                    int col = ncol * 80 + nt * 8 + c2;
                    int e = col >> 4, h = col & 15;
#pragma unroll
                    for (int hh = 0; hh < 2; hh++) {
                        int row = mrow * 32 + mt * 16 + hh * 8 + r4;
                        sm[H1_F + row * 273 + e * 17 + h] =
                            fmaxf(c[mt][nt][hh * 2] + sm[B1T + col], 0.f);
                        sm[H1_F + row * 273 + e * 17 + h + 1] =
                            fmaxf(c[mt][nt][hh * 2 + 1] + sm[B1T + col + 1], 0.f);
                    }
                }
        } else {
#pragma unroll
            for (int mt = 0; mt < 2; mt++) {
#pragma unroll
                for (int nt = 0; nt < 2; nt++) {
                    int col = 240 + nt * 8 + c2;
                    int e = col >> 4, h = col & 15;
#pragma unroll
                    for (int hh = 0; hh < 2; hh++) {
                        int row = mrow * 32 + mt * 16 + hh * 8 + r4;
                        sm[H1_F + row * 273 + e * 17 + h] =
                            fmaxf(c[mt][nt][hh * 2] + sm[B1T + col], 0.f);
                        sm[H1_F + row * 273 + e * 17 + h + 1] =
                            fmaxf(c[mt][nt][hh * 2 + 1] + sm[B1T + col + 1], 0.f);
                    }
                }
#pragma unroll
                for (int nt = 0; nt < 6; nt++) {
                    int gc = nt * 8 + c2;
#pragma unroll
                    for (int hh = 0; hh < 2; hh++) {
                        int row = mrow * 32 + mt * 16 + hh * 8 + r4;
                        sm[LG_F + row * 49 + gc] = c[mt][2 + nt][hh * 2] + sm[BGT + gc];
                        sm[LG_F + row * 49 + gc + 1] = c[mt][2 + nt][hh * 2 + 1] + sm[BGT + gc + 1];
                    }
                }
            }
        }
    }
    // ---- LSE merge (4 threads per row, consecutive lanes) ----
#pragma unroll
    for (int o = 1; o < 4; o <<= 1) {
        float m2 = __shfl_xor_sync(0xffffffffu, lm, o);
        float s2 = __shfl_xor_sync(0xffffffffu, ls, o);
        float nm = fmaxf(lm, m2);
        ls = ls * __expf(lm - nm) + s2 * __expf(m2 - nm);
        lm = nm;
    }
    if (skq == 0) sm[LSET + srow] = lm + __logf(ls);
    __syncthreads();

    if (tid == 0) {
        float s = 0.f;
        for (int r = 0; r < MROWS; r++) s += sm[LSET + r];
        atomicAdd(&g_rz, s);
    }

    // ---- gating + expert layers 2/3 ----
    if (tid < MROWS * TT) {
        int t = tid / MROWS;
        int row = tid - t * MROWS;
        float lg[16];
#pragma unroll
        for (int e = 0; e < 16; e++) lg[e] = sm[LG_F + row * 49 + t * 16 + e];
        int sel[4];
        float sv[4];
#pragma unroll
        for (int k = 0; k < 4; k++) {
            float best = -INFINITY;
            int bi = 0;
#pragma unroll
            for (int e = 0; e < 16; e++)
                if (lg[e] > best) { best = lg[e]; bi = e; }
            sv[k] = best; sel[k] = bi; lg[bi] = -INFINITY;
        }
        float m = sv[0], g4[4], ssum = 0.f;
#pragma unroll
        for (int k = 0; k < 4; k++) { g4[k] = __expf(sv[k] - m); ssum += g4[k]; }
        float inv = 1.f / ssum;
        float y[16];
#pragma unroll
        for (int o = 0; o < 16; o++) y[o] = 0.f;
#pragma unroll
        for (int k = 0; k < 4; k++) {
            int e = sel[k];
            float gk = g4[k] * inv;
            float h[16];
#pragma unroll
            for (int i = 0; i < 16; i++) h[i] = sm[H1_F + row * 273 + e * 17 + i];
            float h2v[8];
#pragma unroll
            for (int j = 0; j < 8; j++) {
                float a = sm[B2T + e * 9 + j];
#pragma unroll
                for (int i = 0; i < 16; i++) a += h[i] * sm[W2T + e * 130 + i * 8 + j];
                h2v[j] = fmaxf(a, 0.f);
            }
#pragma unroll
            for (int o = 0; o < 16; o++) {
                float a = sm[B3T + e * 17 + o];
#pragma unroll
                for (int j = 0; j < 8; j++) a += h2v[j] * sm[W3T + e * 130 + j * 16 + o];
                y[o] += gk * fmaxf(a, 0.f);
            }
            atomicAdd(&sm[IMPT + t * 16 + e], gk);
            atomicAdd(&sm[LDT + t * 16 + e], 1.f);
        }
        float* yo = out + (size_t)t * BN * ON + (size_t)(row0 + row) * ON;
#pragma unroll
        for (int o = 0; o < 16; o++) yo[o] = y[o];
    }
    __syncthreads();
    if (tid < 48) atomicAdd(&g_imp[tid], sm[IMPT + tid]);
    else if (tid < 96) atomicAdd(&g_load[tid - 48], sm[LDT + tid - 48]);
}

__global__ void moe_finalize_kernel(float* __restrict__ out, int out_size) {
    if (threadIdx.x != 0 || blockIdx.x != 0) return;
    float lb = 0.f;
    for (int t = 0; t < TT; t++) {
        float imp[16], ld[16];
        float si = 0.f, sl = 0.f, sil = 0.f;
        for (int e = 0; e < 16; e++) {
            imp[e] = g_imp[t * 16 + e];
            ld[e]  = g_load[t * 16 + e];
            si += imp[e]; sl += ld[e]; sil += imp[e] * ld[e];
        }
        float mi = si / 16.f, ml = sl / 16.f;
        float vi = 0.f, vl = 0.f;
        for (int e = 0; e < 16; e++) {
            float di = imp[e] - mi, dl = ld[e] - ml;
            vi += di * di; vl += dl * dl;
        }
        vi /= 15.f; vl /= 15.f;
        lb += 0.01f * (vi / (mi * mi + 1e-10f) + vl / (ml * ml + 1e-10f))
            + 0.01f * 16.f * sil / (float)BN;
    }
    size_t base = (size_t)TT * BN * ON;
    if (out_size > (int)base)     out[base]     = lb;
    if (out_size > (int)base + 1) out[base + 1] = 3.f * 0.001f * g_rz / (float)BN;
}

extern "C" void kernel_launch(void* const* d_in, const int* in_sizes, int n_in,
                              void* d_out, int out_size) {
    const float* x      = (const float*)d_in[0];
    const float* wgates = (const float*)d_in[1];
    const float* bgates = (const float*)d_in[2];
    const float* W1     = (const float*)d_in[3];
    const float* b1     = (const float*)d_in[4];
    const float* W2     = (const float*)d_in[5];
    const float* b2     = (const float*)d_in[6];
    const float* W3     = (const float*)d_in[7];
    const float* b3     = (const float*)d_in[8];
    float* out = (float*)d_out;

    cudaFuncSetAttribute(moe_mma, cudaFuncAttributeMaxDynamicSharedMemorySize, SMEM_BYTES);

    moe_prep<<<(NCHUNK * 304 * KC + 255) / 256, 256>>>(W1, wgates);
    moe_mma<<<BN / MROWS, NTH, SMEM_BYTES>>>(x, bgates, b1, W2, b2, W3, b3, out);
    moe_finalize_kernel<<<1, 32>>>(out, out_size);
}

// round 10
// speedup vs baseline: 4.4101x; 1.4107x over previous
#include <cuda_runtime.h>
#include <cuda_bf16.h>
#include <cuda_fp16.h>
#include <stdint.h>
#include <math.h>

#define BN 32768
#define DN 512
#define EN 16
#define TT 3
#define ON 16
#define MROWS 128
#define NTH 512
#define NCHUNK 16
#define KC 32
#define CHB 32000           // B chunk bytes: 256*80 (fp16 h1) + 3*48*80 (bf16 gates)
#define GOFF 20480          // gate region offset inside B chunk
#define ATERM 10240         // A per-term bytes (128 rows * 80)
#define ABUF 40960          // A per-buffer: term0 fp16 + 3 bf16 terms
#define BBASE 81920         // B region start (after 2 A buffers); GEMM region ends 145920
// float offsets
#define H1_F 0              // 128*273
#define LG_F 34944          // 128*49
#define B1T 41216
#define BGT 41472
#define W2T 41520
#define W3T 43600
#define B2T 45680
#define B3T 45824
#define IMPT 46096
#define LDT 46144
#define LSET 46192
#define SMEM_BYTES 185344

__device__ __align__(16) unsigned char g_wimg[NCHUNK * CHB];
__device__ float g_imp[TT * EN];
__device__ float g_load[TT * EN];
__device__ float g_rz;

__device__ __forceinline__ uint32_t smem_u32(const void* p) {
    uint32_t a;
    asm("{ .reg .u64 t; cvta.to.shared.u64 t, %1; cvt.u32.u64 %0, t; }" : "=r"(a) : "l"(p));
    return a;
}
__device__ __forceinline__ void ldsm4(uint32_t* r, uint32_t a) {
    asm volatile("ldmatrix.sync.aligned.m8n8.x4.shared.b16 {%0,%1,%2,%3}, [%4];"
                 : "=r"(r[0]), "=r"(r[1]), "=r"(r[2]), "=r"(r[3]) : "r"(a));
}
__device__ __forceinline__ void ldsm2(uint32_t* r, uint32_t a) {
    asm volatile("ldmatrix.sync.aligned.m8n8.x2.shared.b16 {%0,%1}, [%2];"
                 : "=r"(r[0]), "=r"(r[1]) : "r"(a));
}
__device__ __forceinline__ void mmab(float* c, const uint32_t* a, const uint32_t* b) {
    asm volatile("mma.sync.aligned.m16n8k16.row.col.f32.bf16.bf16.f32 "
                 "{%0,%1,%2,%3},{%4,%5,%6,%7},{%8,%9},{%0,%1,%2,%3};"
                 : "+f"(c[0]), "+f"(c[1]), "+f"(c[2]), "+f"(c[3])
                 : "r"(a[0]), "r"(a[1]), "r"(a[2]), "r"(a[3]), "r"(b[0]), "r"(b[1]));
}
__device__ __forceinline__ void mmah(float* c, const uint32_t* a, const uint32_t* b) {
    asm volatile("mma.sync.aligned.m16n8k16.row.col.f32.f16.f16.f32 "
                 "{%0,%1,%2,%3},{%4,%5,%6,%7},{%8,%9},{%0,%1,%2,%3};"
                 : "+f"(c[0]), "+f"(c[1]), "+f"(c[2]), "+f"(c[3])
                 : "r"(a[0]), "r"(a[1]), "r"(a[2]), "r"(a[3]), "r"(b[0]), "r"(b[1]));
}
__device__ __forceinline__ void cpa16(uint32_t d, const void* s) {
    asm volatile("cp.async.cg.shared.global [%0], [%1], 16;" :: "r"(d), "l"(s) : "memory");
}

// ---------- prepass: h1 weights -> fp16 single; gate weights -> bf16 3-way split ----------
__global__ void moe_prep(const float* __restrict__ W1, const float* __restrict__ wg) {
    if (blockIdx.x == 0) {
        int i = threadIdx.x;
        if (i < TT * EN) { g_imp[i] = 0.f; g_load[i] = 0.f; }
        if (i == 0) g_rz = 0.f;
    }
    int idx = blockIdx.x * blockDim.x + threadIdx.x;
    if (idx >= NCHUNK * 304 * KC) return;
    int c = idx / (304 * KC);
    int r = idx - c * (304 * KC);
    int n = r >> 5, k = r & 31, d = c * KC + k;
    unsigned char* base = g_wimg + (size_t)c * CHB;
    if (n < 256) {
        float w = W1[(n >> 4) * (DN * 16) + d * 16 + (n & 15)];
        *(__half*)(base + n * 80 + 2 * k) = __float2half_rn(w);
    } else {
        int gn = n - 256;
        float w = wg[(gn >> 4) * (DN * EN) + d * 16 + (gn & 15)];
        __nv_bfloat16 t0 = __float2bfloat16(w);
        float r1 = w - __bfloat162float(t0);
        __nv_bfloat16 t1 = __float2bfloat16(r1);
        __nv_bfloat16 t2 = __float2bfloat16(r1 - __bfloat162float(t1));
        *(__nv_bfloat16*)(base + GOFF + gn * 80 + 2 * k) = t0;
        *(__nv_bfloat16*)(base + GOFF + 3840 + gn * 80 + 2 * k) = t1;
        *(__nv_bfloat16*)(base + GOFF + 7680 + gn * 80 + 2 * k) = t2;
    }
}

// ---------- main ----------
extern __shared__ float sm[];

__global__ __launch_bounds__(NTH, 1)
void moe_mma(const float* __restrict__ x,
             const float* __restrict__ bgates,
             const float* __restrict__ b1,
             const float* __restrict__ W2,
             const float* __restrict__ b2,
             const float* __restrict__ W3,
             const float* __restrict__ b3,
             float* __restrict__ out) {
    const int tid = threadIdx.x;
    const int wid = tid >> 5, l = tid & 31;
    const int mrow = wid & 3, ncol = wid >> 2;
    const int row0 = blockIdx.x * MROWS;
    const uint32_t sb = smem_u32(sm);

    for (int i = tid; i < 256; i += NTH) sm[B1T + i] = b1[i];
    if (tid < 48) { sm[BGT + tid] = bgates[tid]; sm[IMPT + tid] = 0.f; sm[LDT + tid] = 0.f; }
    for (int i = tid; i < 2048; i += NTH) {
        sm[W2T + (i >> 7) * 130 + (i & 127)] = W2[i];
        sm[W3T + (i >> 7) * 130 + (i & 127)] = W3[i];
    }
    for (int i = tid; i < 128; i += NTH) sm[B2T + (i >> 3) * 9 + (i & 7)] = b2[i];
    for (int i = tid; i < 256; i += NTH) sm[B3T + (i >> 4) * 17 + (i & 15)] = b3[i];

    float c[2][10][4];
#pragma unroll
    for (int i = 0; i < 2; i++)
#pragma unroll
        for (int j = 0; j < 10; j++)
#pragma unroll
            for (int q = 0; q < 4; q++) c[i][j][q] = 0.f;

    const uint32_t aoff = (uint32_t)((mrow * 32 + ((l >> 3) & 1) * 8 + (l & 7)) * 80 + (l >> 4) * 16);
    const uint32_t boff = (uint32_t)((l & 7) * 80 + ((l >> 3) & 1) * 16);
    const uint32_t boff4 = boff + (uint32_t)(l >> 4) * 640;   // x4: lanes 16-31 -> next n-tile
    const int srow = tid >> 2, skq = tid & 3;
    const float* xp = x + (size_t)(row0 + srow) * DN + skq * 8;
    const uint32_t stoff = (uint32_t)(srow * 80 + skq * 16);
    float lm = -INFINITY, ls = 0.f;
    float4 xa, xb;

#define STAGE_B(ch_, bq) do {                                                  \
    const unsigned char* s_ = g_wimg + (size_t)(ch_) * CHB;                    \
    uint32_t d_ = sb + BBASE + (bq) * CHB;                                     \
    _Pragma("unroll") for (int j_ = 0; j_ < 4; j_++) {                         \
        uint32_t o_ = (uint32_t)tid * 16 + j_ * 8192;                          \
        if (o_ < CHB) cpa16(d_ + o_, s_ + o_);                                 \
    }                                                                          \
    asm volatile("cp.async.commit_group;" ::: "memory"); } while (0)

#define STAGE_A(bq) do {                                                       \
    float v_[8] = {xa.x, xa.y, xa.z, xa.w, xb.x, xb.y, xb.z, xb.w};            \
    float cm_ = v_[0];                                                         \
    _Pragma("unroll") for (int i_ = 1; i_ < 8; i_++) cm_ = fmaxf(cm_, v_[i_]); \
    float nm_ = fmaxf(lm, cm_);                                                \
    ls *= __expf(lm - nm_);                                                    \
    float ad_ = 0.f;                                                           \
    _Pragma("unroll") for (int i_ = 0; i_ < 8; i_++) ad_ += __expf(v_[i_] - nm_); \
    ls += ad_; lm = nm_;                                                       \
    {   uint32_t rh_[4];                                                       \
        _Pragma("unroll") for (int i_ = 0; i_ < 4; i_++) {                     \
            __half h0_ = __float2half_rn(v_[2 * i_]);                          \
            __half h1_ = __float2half_rn(v_[2 * i_ + 1]);                      \
            rh_[i_] = ((uint32_t)__half_as_ushort(h1_) << 16) |                \
                      (uint32_t)__half_as_ushort(h0_);                         \
        }                                                                      \
        asm volatile("st.shared.v4.b32 [%0], {%1,%2,%3,%4};"                   \
            :: "r"(sb + (bq) * ABUF + stoff),                                  \
               "r"(rh_[0]), "r"(rh_[1]), "r"(rh_[2]), "r"(rh_[3]) : "memory"); \
    }                                                                          \
    _Pragma("unroll") for (int t_ = 0; t_ < 3; t_++) {                         \
        uint32_t rr_[4];                                                       \
        _Pragma("unroll") for (int i_ = 0; i_ < 4; i_++) {                     \
            __nv_bfloat16 p0_ = __float2bfloat16(v_[2 * i_]);                  \
            __nv_bfloat16 p1_ = __float2bfloat16(v_[2 * i_ + 1]);              \
            v_[2 * i_]     -= __bfloat162float(p0_);                           \
            v_[2 * i_ + 1] -= __bfloat162float(p1_);                           \
            rr_[i_] = ((uint32_t)__bfloat16_as_ushort(p1_) << 16) |            \
                      (uint32_t)__bfloat16_as_ushort(p0_);                     \
        }                                                                      \
        asm volatile("st.shared.v4.b32 [%0], {%1,%2,%3,%4};"                   \
            :: "r"(sb + (bq) * ABUF + (t_ + 1) * ATERM + stoff),               \
               "r"(rr_[0]), "r"(rr_[1]), "r"(rr_[2]), "r"(rr_[3]) : "memory"); \
    } } while (0)

    xa = *(const float4*)xp;
    xb = *(const float4*)(xp + 4);
    STAGE_B(0, 0);
    STAGE_A(0);

    for (int ch = 0; ch < NCHUNK; ++ch) {
        int buf = ch & 1;
        if (ch < NCHUNK - 1) {
            const float* xq = xp + (ch + 1) * KC;
            xa = *(const float4*)xq;
            xb = *(const float4*)(xq + 4);
        }
        asm volatile("cp.async.wait_group 0;" ::: "memory");
        __syncthreads();
        if (ch < NCHUNK - 1) STAGE_B(ch + 1, buf ^ 1);

        {
            uint32_t Ab = sb + buf * ABUF;
            uint32_t Bb = sb + BBASE + buf * CHB;
            if (ncol < 3) {
                // h1 tiles: single fp16 term, paired-n ldsm4 B loads
#pragma unroll
                for (int ks = 0; ks < 2; ++ks) {
                    uint32_t a[2][4];
#pragma unroll
                    for (int mt = 0; mt < 2; mt++)
                        ldsm4(a[mt], Ab + aoff + mt * 1280 + ks * 32);
#pragma unroll
                    for (int np = 0; np < 5; ++np) {
                        uint32_t b[4];
                        ldsm4(b, Bb + (uint32_t)((ncol * 80 + np * 16) * 80) + boff4 + ks * 32);
#pragma unroll
                        for (int mt = 0; mt < 2; mt++) {
                            mmah(c[mt][2 * np], a[mt], b);
                            mmah(c[mt][2 * np + 1], a[mt], b + 2);
                        }
                    }
                }
            } else {
#pragma unroll
                for (int ks = 0; ks < 2; ++ks) {
                    uint32_t ah[2][4], ag[3][2][4];
#pragma unroll
                    for (int mt = 0; mt < 2; mt++)
                        ldsm4(ah[mt], Ab + aoff + mt * 1280 + ks * 32);
#pragma unroll
                    for (int t = 0; t < 3; t++)
#pragma unroll
                        for (int mt = 0; mt < 2; mt++)
                            ldsm4(ag[t][mt], Ab + (t + 1) * ATERM + aoff + mt * 1280 + ks * 32);
                    // leftover h1 cols 240-255 (fp16)
#pragma unroll
                    for (int nt = 0; nt < 2; ++nt) {
                        uint32_t b[2];
                        ldsm2(b, Bb + (uint32_t)((240 + nt * 8) * 80) + boff + ks * 32);
#pragma unroll
                        for (int mt = 0; mt < 2; mt++) mmah(c[mt][nt], ah[mt], b);
                    }
                    // gates: 6-term bf16
#pragma unroll
                    for (int nt = 0; nt < 6; ++nt) {
                        uint32_t b0[2], b1[2], b2[2];
                        uint32_t ba = Bb + GOFF + (uint32_t)(nt * 8 * 80) + boff + ks * 32;
                        ldsm2(b0, ba);
                        ldsm2(b1, ba + 3840);
                        ldsm2(b2, ba + 7680);
#pragma unroll
                        for (int mt = 0; mt < 2; mt++) {
                            float* cc = c[mt][2 + nt];
                            mmab(cc, ag[0][mt], b0);
                            mmab(cc, ag[0][mt], b1);
                            mmab(cc, ag[1][mt], b0);
                            mmab(cc, ag[1][mt], b1);
                            mmab(cc, ag[0][mt], b2);
                            mmab(cc, ag[2][mt], b0);
                        }
                    }
                }
            }
        }
        if (ch < NCHUNK - 1) STAGE_A(buf ^ 1);
    }
    __syncthreads();

    // ---- C writeback: bias + relu into padded epilogue smem ----
    {
        int r4 = l >> 2, c2 = 2 * (l & 3);
        if (ncol < 3) {
#pragma unroll
            for (int mt = 0; mt < 2; mt++)
#pragma unroll
                for (int nt = 0; nt < 10; nt++) {
                    int col = ncol * 80 + nt * 8 + c2;
                    int e = col >> 4, h = col & 15;
#pragma unroll
                    for (int hh = 0; hh < 2; hh++) {
                        int row = mrow * 32 + mt * 16 + hh * 8 + r4;
                        sm[H1_F + row * 273 + e * 17 + h] =
                            fmaxf(c[mt][nt][hh * 2] + sm[B1T + col], 0.f);
                        sm[H1_F + row * 273 + e * 17 + h + 1] =
                            fmaxf(c[mt][nt][hh * 2 + 1] + sm[B1T + col + 1], 0.f);
                    }
                }
        } else {
#pragma unroll
            for (int mt = 0; mt < 2; mt++) {
#pragma unroll
                for (int nt = 0; nt < 2; nt++) {
                    int col = 240 + nt * 8 + c2;
                    int e = col >> 4, h = col & 15;
#pragma unroll
                    for (int hh = 0; hh < 2; hh++) {
                        int row = mrow * 32 + mt * 16 + hh * 8 + r4;
                        sm[H1_F + row * 273 + e * 17 + h] =
                            fmaxf(c[mt][nt][hh * 2] + sm[B1T + col], 0.f);
                        sm[H1_F + row * 273 + e * 17 + h + 1] =
                            fmaxf(c[mt][nt][hh * 2 + 1] + sm[B1T + col + 1], 0.f);
                    }
                }
#pragma unroll
                for (int nt = 0; nt < 6; nt++) {
                    int gc = nt * 8 + c2;
#pragma unroll
                    for (int hh = 0; hh < 2; hh++) {
                        int row = mrow * 32 + mt * 16 + hh * 8 + r4;
                        sm[LG_F + row * 49 + gc] = c[mt][2 + nt][hh * 2] + sm[BGT + gc];
                        sm[LG_F + row * 49 + gc + 1] = c[mt][2 + nt][hh * 2 + 1] + sm[BGT + gc + 1];
                    }
                }
            }
        }
    }
    // ---- LSE merge (4 threads per row) ----
#pragma unroll
    for (int o = 1; o < 4; o <<= 1) {
        float m2 = __shfl_xor_sync(0xffffffffu, lm, o);
        float s2 = __shfl_xor_sync(0xffffffffu, ls, o);
        float nm = fmaxf(lm, m2);
        ls = ls * __expf(lm - nm) + s2 * __expf(m2 - nm);
        lm = nm;
    }
    if (skq == 0) sm[LSET + srow] = lm + __logf(ls);
    __syncthreads();

    if (tid == 0) {
        float s = 0.f;
        for (int r = 0; r < MROWS; r++) s += sm[LSET + r];
        atomicAdd(&g_rz, s);
    }

    // ---- gating + expert layers 2/3 ----
    if (tid < MROWS * TT) {
        int t = tid / MROWS;
        int row = tid - t * MROWS;
        float lg[16];
#pragma unroll
        for (int e = 0; e < 16; e++) lg[e] = sm[LG_F + row * 49 + t * 16 + e];
        int sel[4];
        float sv[4];
#pragma unroll
        for (int k = 0; k < 4; k++) {
            float best = -INFINITY;
            int bi = 0;
#pragma unroll
            for (int e = 0; e < 16; e++)
                if (lg[e] > best) { best = lg[e]; bi = e; }
            sv[k] = best; sel[k] = bi; lg[bi] = -INFINITY;
        }
        float m = sv[0], g4[4], ssum = 0.f;
#pragma unroll
        for (int k = 0; k < 4; k++) { g4[k] = __expf(sv[k] - m); ssum += g4[k]; }
        float inv = 1.f / ssum;
        float y[16];
#pragma unroll
        for (int o = 0; o < 16; o++) y[o] = 0.f;
#pragma unroll
        for (int k = 0; k < 4; k++) {
            int e = sel[k];
            float gk = g4[k] * inv;
            float h[16];
#pragma unroll
            for (int i = 0; i < 16; i++) h[i] = sm[H1_F + row * 273 + e * 17 + i];
            float h2v[8];
#pragma unroll
            for (int j = 0; j < 8; j++) {
                float a = sm[B2T + e * 9 + j];
#pragma unroll
                for (int i = 0; i < 16; i++) a += h[i] * sm[W2T + e * 130 + i * 8 + j];
                h2v[j] = fmaxf(a, 0.f);
            }
#pragma unroll
            for (int o = 0; o < 16; o++) {
                float a = sm[B3T + e * 17 + o];
#pragma unroll
                for (int j = 0; j < 8; j++) a += h2v[j] * sm[W3T + e * 130 + j * 16 + o];
                y[o] += gk * fmaxf(a, 0.f);
            }
            atomicAdd(&sm[IMPT + t * 16 + e], gk);
            atomicAdd(&sm[LDT + t * 16 + e], 1.f);
        }
        float* yo = out + (size_t)t * BN * ON + (size_t)(row0 + row) * ON;
#pragma unroll
        for (int o = 0; o < 16; o++) yo[o] = y[o];
    }
    __syncthreads();
    if (tid < 48) atomicAdd(&g_imp[tid], sm[IMPT + tid]);
    else if (tid < 96) atomicAdd(&g_load[tid - 48], sm[LDT + tid - 48]);
}

__global__ void moe_finalize_kernel(float* __restrict__ out, int out_size) {
    if (threadIdx.x != 0 || blockIdx.x != 0) return;
    float lb = 0.f;
    for (int t = 0; t < TT; t++) {
        float imp[16], ld[16];
        float si = 0.f, sl = 0.f, sil = 0.f;
        for (int e = 0; e < 16; e++) {
            imp[e] = g_imp[t * 16 + e];
            ld[e]  = g_load[t * 16 + e];
            si += imp[e]; sl += ld[e]; sil += imp[e] * ld[e];
        }
        float mi = si / 16.f, ml = sl / 16.f;
        float vi = 0.f, vl = 0.f;
        for (int e = 0; e < 16; e++) {
            float di = imp[e] - mi, dl = ld[e] - ml;
            vi += di * di; vl += dl * dl;
        }
        vi /= 15.f; vl /= 15.f;
        lb += 0.01f * (vi / (mi * mi + 1e-10f) + vl / (ml * ml + 1e-10f))
            + 0.01f * 16.f * sil / (float)BN;
    }
    size_t base = (size_t)TT * BN * ON;
    if (out_size > (int)base)     out[base]     = lb;
    if (out_size > (int)base + 1) out[base + 1] = 3.f * 0.001f * g_rz / (float)BN;
}

extern "C" void kernel_launch(void* const* d_in, const int* in_sizes, int n_in,
                              void* d_out, int out_size) {
    const float* x      = (const float*)d_in[0];
    const float* wgates = (const float*)d_in[1];
    const float* bgates = (const float*)d_in[2];
    const float* W1     = (const float*)d_in[3];
    const float* b1     = (const float*)d_in[4];
    const float* W2     = (const float*)d_in[5];
    const float* b2     = (const float*)d_in[6];
    const float* W3     = (const float*)d_in[7];
    const float* b3     = (const float*)d_in[8];
    float* out = (float*)d_out;

    cudaFuncSetAttribute(moe_mma, cudaFuncAttributeMaxDynamicSharedMemorySize, SMEM_BYTES);

    moe_prep<<<(NCHUNK * 304 * KC + 255) / 256, 256>>>(W1, wgates);
    moe_mma<<<BN / MROWS, NTH, SMEM_BYTES>>>(x, bgates, b1, W2, b2, W3, b3, out);
    moe_finalize_kernel<<<1, 32>>>(out, out_size);
}

// round 14
// speedup vs baseline: 5.2306x; 1.1860x over previous
#include <cuda_runtime.h>
#include <cuda_bf16.h>
#include <cuda_fp16.h>
#include <stdint.h>
#include <math.h>

#define BN 32768
#define DN 512
#define EN 16
#define TT 3
#define ON 16
#define MROWS 128
#define NTH 512
#define NCHUNK 16
#define KC 32
#define CHB 28160           // B chunk bytes: 256*80 (fp16 h1) + 2*48*80 (fp16 gates)
#define GOFF 20480          // gate region offset inside B chunk
#define ATERM 10240         // A per-term bytes (128 rows * 80)
#define ABUF 20480          // A per-buffer: 2 fp16 terms
#define BBASE 40960         // B region start (after 2 A buffers)
// float offsets (epilogue layout identical to R10)
#define H1_F 0              // 128*273
#define LG_F 34944          // 128*49
#define B1T 41216
#define BGT 41472
#define W2T 41520
#define W3T 43600
#define B2T 45680
#define B3T 45824
#define IMPT 46096
#define LDT 46144
#define LSET 46192
#define SMEM_BYTES 185344

__device__ __align__(16) unsigned char g_wimg[NCHUNK * CHB];
__device__ float g_imp[TT * EN];
__device__ float g_load[TT * EN];
__device__ float g_rz;

__device__ __forceinline__ uint32_t smem_u32(const void* p) {
    uint32_t a;
    asm("{ .reg .u64 t; cvta.to.shared.u64 t, %1; cvt.u32.u64 %0, t; }" : "=r"(a) : "l"(p));
    return a;
}
__device__ __forceinline__ void ldsm4(uint32_t* r, uint32_t a) {
    asm volatile("ldmatrix.sync.aligned.m8n8.x4.shared.b16 {%0,%1,%2,%3}, [%4];"
                 : "=r"(r[0]), "=r"(r[1]), "=r"(r[2]), "=r"(r[3]) : "r"(a));
}
__device__ __forceinline__ void ldsm2(uint32_t* r, uint32_t a) {
    asm volatile("ldmatrix.sync.aligned.m8n8.x2.shared.b16 {%0,%1}, [%2];"
                 : "=r"(r[0]), "=r"(r[1]) : "r"(a));
}
__device__ __forceinline__ void mmah(float* c, const uint32_t* a, const uint32_t* b) {
    asm volatile("mma.sync.aligned.m16n8k16.row.col.f32.f16.f16.f32 "
                 "{%0,%1,%2,%3},{%4,%5,%6,%7},{%8,%9},{%0,%1,%2,%3};"
                 : "+f"(c[0]), "+f"(c[1]), "+f"(c[2]), "+f"(c[3])
                 : "r"(a[0]), "r"(a[1]), "r"(a[2]), "r"(a[3]), "r"(b[0]), "r"(b[1]));
}
__device__ __forceinline__ void cpa16(uint32_t d, const void* s) {
    asm volatile("cp.async.cg.shared.global [%0], [%1], 16;" :: "r"(d), "l"(s) : "memory");
}

// ---------- prepass: h1 weights -> fp16 single; gate weights -> fp16 2-term split ----------
__global__ void moe_prep(const float* __restrict__ W1, const float* __restrict__ wg) {
    if (blockIdx.x == 0) {
        int i = threadIdx.x;
        if (i < TT * EN) { g_imp[i] = 0.f; g_load[i] = 0.f; }
        if (i == 0) g_rz = 0.f;
    }
    int idx = blockIdx.x * blockDim.x + threadIdx.x;
    if (idx >= NCHUNK * 304 * KC) return;
    int c = idx / (304 * KC);
    int r = idx - c * (304 * KC);
    int n = r >> 5, k = r & 31, d = c * KC + k;
    unsigned char* base = g_wimg + (size_t)c * CHB;
    if (n < 256) {
        float w = W1[(n >> 4) * (DN * 16) + d * 16 + (n & 15)];
        *(__half*)(base + n * 80 + 2 * k) = __float2half_rn(w);
    } else {
        int gn = n - 256;
        float w = wg[(gn >> 4) * (DN * EN) + d * 16 + (gn & 15)];
        __half t0 = __float2half_rn(w);
        __half t1 = __float2half_rn(w - __half2float(t0));
        *(__half*)(base + GOFF + gn * 80 + 2 * k) = t0;
        *(__half*)(base + GOFF + 3840 + gn * 80 + 2 * k) = t1;
    }
}

// ---------- main ----------
extern __shared__ float sm[];

__global__ __launch_bounds__(NTH, 1)
void moe_mma(const float* __restrict__ x,
             const float* __restrict__ bgates,
             const float* __restrict__ b1,
             const float* __restrict__ W2,
             const float* __restrict__ b2,
             const float* __restrict__ W3,
             const float* __restrict__ b3,
             float* __restrict__ out) {
    const int tid = threadIdx.x;
    const int wid = tid >> 5, l = tid & 31;
    const int mrow = wid & 3, ncol = wid >> 2;
    const int row0 = blockIdx.x * MROWS;
    const uint32_t sb = smem_u32(sm);

    for (int i = tid; i < 256; i += NTH) sm[B1T + i] = b1[i];
    if (tid < 48) { sm[BGT + tid] = bgates[tid]; sm[IMPT + tid] = 0.f; sm[LDT + tid] = 0.f; }
    for (int i = tid; i < 2048; i += NTH) {
        sm[W2T + (i >> 7) * 130 + (i & 127)] = W2[i];
        sm[W3T + (i >> 7) * 130 + (i & 127)] = W3[i];
    }
    for (int i = tid; i < 128; i += NTH) sm[B2T + (i >> 3) * 9 + (i & 7)] = b2[i];
    for (int i = tid; i < 256; i += NTH) sm[B3T + (i >> 4) * 17 + (i & 15)] = b3[i];

    float c[2][10][4];
#pragma unroll
    for (int i = 0; i < 2; i++)
#pragma unroll
        for (int j = 0; j < 10; j++)
#pragma unroll
            for (int q = 0; q < 4; q++) c[i][j][q] = 0.f;

    const uint32_t aoff = (uint32_t)((mrow * 32 + ((l >> 3) & 1) * 8 + (l & 7)) * 80 + (l >> 4) * 16);
    const uint32_t boff = (uint32_t)((l & 7) * 80 + ((l >> 3) & 1) * 16);
    const uint32_t boff4 = boff + (uint32_t)(l >> 4) * 640;   // x4: lanes 16-31 -> next n-tile
    const int srow = tid >> 2, skq = tid & 3;
    const float* xp = x + (size_t)(row0 + srow) * DN + skq * 8;
    const uint32_t stoff = (uint32_t)(srow * 80 + skq * 16);
    float lm = -INFINITY, ls = 0.f;
    float4 xa, xb;

#define STAGE_B(ch_, bq) do {                                                  \
    const unsigned char* s_ = g_wimg + (size_t)(ch_) * CHB;                    \
    uint32_t d_ = sb + BBASE + (bq) * CHB;                                     \
    _Pragma("unroll") for (int j_ = 0; j_ < 4; j_++) {                         \
        uint32_t o_ = (uint32_t)tid * 16 + j_ * 8192;                          \
        if (o_ < CHB) cpa16(d_ + o_, s_ + o_);                                 \
    }                                                                          \
    asm volatile("cp.async.commit_group;" ::: "memory"); } while (0)

#define STAGE_A(bq) do {                                                       \
    float v_[8] = {xa.x, xa.y, xa.z, xa.w, xb.x, xb.y, xb.z, xb.w};            \
    float cm_ = v_[0];                                                         \
    _Pragma("unroll") for (int i_ = 1; i_ < 8; i_++) cm_ = fmaxf(cm_, v_[i_]); \
    float nm_ = fmaxf(lm, cm_);                                                \
    ls *= __expf(lm - nm_);                                                    \
    float ad_ = 0.f;                                                           \
    _Pragma("unroll") for (int i_ = 0; i_ < 8; i_++) ad_ += __expf(v_[i_] - nm_); \
    ls += ad_; lm = nm_;                                                       \
    uint32_t r0_[4], r1_[4];                                                   \
    _Pragma("unroll") for (int i_ = 0; i_ < 4; i_++) {                         \
        __half h0_ = __float2half_rn(v_[2 * i_]);                              \
        __half h1_ = __float2half_rn(v_[2 * i_ + 1]);                          \
        r0_[i_] = ((uint32_t)__half_as_ushort(h1_) << 16) |                    \
                  (uint32_t)__half_as_ushort(h0_);                             \
        __half d0_ = __float2half_rn(v_[2 * i_] - __half2float(h0_));          \
        __half d1_ = __float2half_rn(v_[2 * i_ + 1] - __half2float(h1_));      \
        r1_[i_] = ((uint32_t)__half_as_ushort(d1_) << 16) |                    \
                  (uint32_t)__half_as_ushort(d0_);                             \
    }                                                                          \
    asm volatile("st.shared.v4.b32 [%0], {%1,%2,%3,%4};"                       \
        :: "r"(sb + (bq) * ABUF + stoff),                                      \
           "r"(r0_[0]), "r"(r0_[1]), "r"(r0_[2]), "r"(r0_[3]) : "memory");     \
    asm volatile("st.shared.v4.b32 [%0], {%1,%2,%3,%4};"                       \
        :: "r"(sb + (bq) * ABUF + ATERM + stoff),                              \
           "r"(r1_[0]), "r"(r1_[1]), "r"(r1_[2]), "r"(r1_[3]) : "memory");     \
    } while (0)

    xa = *(const float4*)xp;
    xb = *(const float4*)(xp + 4);
    STAGE_B(0, 0);
    STAGE_A(0);

    for (int ch = 0; ch < NCHUNK; ++ch) {
        int buf = ch & 1;
        if (ch < NCHUNK - 1) {
            const float* xq = xp + (ch + 1) * KC;
            xa = *(const float4*)xq;
            xb = *(const float4*)(xq + 4);
        }
        asm volatile("cp.async.wait_group 0;" ::: "memory");
        __syncthreads();
        if (ch < NCHUNK - 1) STAGE_B(ch + 1, buf ^ 1);

        {
            uint32_t Ab = sb + buf * ABUF;
            uint32_t Bb = sb + BBASE + buf * CHB;
            if (ncol < 3) {
                // h1 tiles: single fp16 term, paired-n ldsm4 B loads
#pragma unroll
                for (int ks = 0; ks < 2; ++ks) {
                    uint32_t a[2][4];
#pragma unroll
                    for (int mt = 0; mt < 2; mt++)
                        ldsm4(a[mt], Ab + aoff + mt * 1280 + ks * 32);
#pragma unroll
                    for (int np = 0; np < 5; ++np) {
                        uint32_t b[4];
                        ldsm4(b, Bb + (uint32_t)((ncol * 80 + np * 16) * 80) + boff4 + ks * 32);
#pragma unroll
                        for (int mt = 0; mt < 2; mt++) {
                            mmah(c[mt][2 * np], a[mt], b);
                            mmah(c[mt][2 * np + 1], a[mt], b + 2);
                        }
                    }
                }
            } else {
#pragma unroll
                for (int ks = 0; ks < 2; ++ks) {
                    uint32_t a0[2][4], a1[2][4];
#pragma unroll
                    for (int mt = 0; mt < 2; mt++) {
                        ldsm4(a0[mt], Ab + aoff + mt * 1280 + ks * 32);
                        ldsm4(a1[mt], Ab + ATERM + aoff + mt * 1280 + ks * 32);
                    }
                    // leftover h1 cols 240-255 (fp16 term0)
#pragma unroll
                    for (int nt = 0; nt < 2; ++nt) {
                        uint32_t b[2];
                        ldsm2(b, Bb + (uint32_t)((240 + nt * 8) * 80) + boff + ks * 32);
#pragma unroll
                        for (int mt = 0; mt < 2; mt++) mmah(c[mt][nt], a0[mt], b);
                    }
                    // gates: fp16 2-term split, 3 combos
#pragma unroll
                    for (int nt = 0; nt < 6; ++nt) {
                        uint32_t b0[2], b1[2];
                        uint32_t ba = Bb + GOFF + (uint32_t)(nt * 8 * 80) + boff + ks * 32;
                        ldsm2(b0, ba);
                        ldsm2(b1, ba + 3840);
#pragma unroll
                        for (int mt = 0; mt < 2; mt++) {
                            float* cc = c[mt][2 + nt];
                            mmah(cc, a0[mt], b0);
                            mmah(cc, a0[mt], b1);
                            mmah(cc, a1[mt], b0);
                        }
                    }
                }
            }
        }
        if (ch < NCHUNK - 1) STAGE_A(buf ^ 1);
    }
    __syncthreads();

    // ---- C writeback: bias + relu into padded epilogue smem ----
    {
        int r4 = l >> 2, c2 = 2 * (l & 3);
        if (ncol < 3) {
#pragma unroll
            for (int mt = 0; mt < 2; mt++)
#pragma unroll
                for (int nt = 0; nt < 10; nt++) {
                    int col = ncol * 80 + nt * 8 + c2;
                    int e = col >> 4, h = col & 15;
#pragma unroll
                    for (int hh = 0; hh < 2; hh++) {
                        int row = mrow * 32 + mt * 16 + hh * 8 + r4;
                        sm[H1_F + row * 273 + e * 17 + h] =
                            fmaxf(c[mt][nt][hh * 2] + sm[B1T + col], 0.f);
                        sm[H1_F + row * 273 + e * 17 + h + 1] =
                            fmaxf(c[mt][nt][hh * 2 + 1] + sm[B1T + col + 1], 0.f);
                    }
                }
        } else {
#pragma unroll
            for (int mt = 0; mt < 2; mt++) {
#pragma unroll
                for (int nt = 0; nt < 2; nt++) {
                    int col = 240 + nt * 8 + c2;
                    int e = col >> 4, h = col & 15;
#pragma unroll
                    for (int hh = 0; hh < 2; hh++) {
                        int row = mrow * 32 + mt * 16 + hh * 8 + r4;
                        sm[H1_F + row * 273 + e * 17 + h] =
                            fmaxf(c[mt][nt][hh * 2] + sm[B1T + col], 0.f);
                        sm[H1_F + row * 273 + e * 17 + h + 1] =
                            fmaxf(c[mt][nt][hh * 2 + 1] + sm[B1T + col + 1], 0.f);
                    }
                }
#pragma unroll
                for (int nt = 0; nt < 6; nt++) {
                    int gc = nt * 8 + c2;
#pragma unroll
                    for (int hh = 0; hh < 2; hh++) {
                        int row = mrow * 32 + mt * 16 + hh * 8 + r4;
                        sm[LG_F + row * 49 + gc] = c[mt][2 + nt][hh * 2] + sm[BGT + gc];
                        sm[LG_F + row * 49 + gc + 1] = c[mt][2 + nt][hh * 2 + 1] + sm[BGT + gc + 1];
                    }
                }
            }
        }
    }
    // ---- LSE merge (4 threads per row) ----
#pragma unroll
    for (int o = 1; o < 4; o <<= 1) {
        float m2 = __shfl_xor_sync(0xffffffffu, lm, o);
        float s2 = __shfl_xor_sync(0xffffffffu, ls, o);
        float nm = fmaxf(lm, m2);
        ls = ls * __expf(lm - nm) + s2 * __expf(m2 - nm);
        lm = nm;
    }
    if (skq == 0) sm[LSET + srow] = lm + __logf(ls);
    __syncthreads();

    if (tid == 0) {
        float s = 0.f;
        for (int r = 0; r < MROWS; r++) s += sm[LSET + r];
        atomicAdd(&g_rz, s);
    }

    // ---- gating + expert layers 2/3 ----
    if (tid < MROWS * TT) {
        int t = tid / MROWS;
        int row = tid - t * MROWS;
        float lg[16];
#pragma unroll
        for (int e = 0; e < 16; e++) lg[e] = sm[LG_F + row * 49 + t * 16 + e];
        int sel[4];
        float sv[4];
#pragma unroll
        for (int k = 0; k < 4; k++) {
            float best = -INFINITY;
            int bi = 0;
#pragma unroll
            for (int e = 0; e < 16; e++)
                if (lg[e] > best) { best = lg[e]; bi = e; }
            sv[k] = best; sel[k] = bi; lg[bi] = -INFINITY;
        }
        float m = sv[0], g4[4], ssum = 0.f;
#pragma unroll
        for (int k = 0; k < 4; k++) { g4[k] = __expf(sv[k] - m); ssum += g4[k]; }
        float inv = 1.f / ssum;
        float y[16];
#pragma unroll
        for (int o = 0; o < 16; o++) y[o] = 0.f;
#pragma unroll
        for (int k = 0; k < 4; k++) {
            int e = sel[k];
            float gk = g4[k] * inv;
            float h[16];
#pragma unroll
            for (int i = 0; i < 16; i++) h[i] = sm[H1_F + row * 273 + e * 17 + i];
            float h2v[8];
#pragma unroll
            for (int j = 0; j < 8; j++) {
                float a = sm[B2T + e * 9 + j];
#pragma unroll
                for (int i = 0; i < 16; i++) a += h[i] * sm[W2T + e * 130 + i * 8 + j];
                h2v[j] = fmaxf(a, 0.f);
            }
#pragma unroll
            for (int o = 0; o < 16; o++) {
                float a = sm[B3T + e * 17 + o];
#pragma unroll
                for (int j = 0; j < 8; j++) a += h2v[j] * sm[W3T + e * 130 + j * 16 + o];
                y[o] += gk * fmaxf(a, 0.f);
            }
            atomicAdd(&sm[IMPT + t * 16 + e], gk);
            atomicAdd(&sm[LDT + t * 16 + e], 1.f);
        }
        float* yo = out + (size_t)t * BN * ON + (size_t)(row0 + row) * ON;
#pragma unroll
        for (int o = 0; o < 16; o++) yo[o] = y[o];
    }
    __syncthreads();
    if (tid < 48) atomicAdd(&g_imp[tid], sm[IMPT + tid]);
    else if (tid < 96) atomicAdd(&g_load[tid - 48], sm[LDT + tid - 48]);
}

__global__ void moe_finalize_kernel(float* __restrict__ out, int out_size) {
    if (threadIdx.x != 0 || blockIdx.x != 0) return;
    float lb = 0.f;
    for (int t = 0; t < TT; t++) {
        float imp[16], ld[16];
        float si = 0.f, sl = 0.f, sil = 0.f;
        for (int e = 0; e < 16; e++) {
            imp[e] = g_imp[t * 16 + e];
            ld[e]  = g_load[t * 16 + e];
            si += imp[e]; sl += ld[e]; sil += imp[e] * ld[e];
        }
        float mi = si / 16.f, ml = sl / 16.f;
        float vi = 0.f, vl = 0.f;
        for (int e = 0; e < 16; e++) {
            float di = imp[e] - mi, dl = ld[e] - ml;
            vi += di * di; vl += dl * dl;
        }
        vi /= 15.f; vl /= 15.f;
        lb += 0.01f * (vi / (mi * mi + 1e-10f) + vl / (ml * ml + 1e-10f))
            + 0.01f * 16.f * sil / (float)BN;
    }
    size_t base = (size_t)TT * BN * ON;
    if (out_size > (int)base)     out[base]     = lb;
    if (out_size > (int)base + 1) out[base + 1] = 3.f * 0.001f * g_rz / (float)BN;
}

extern "C" void kernel_launch(void* const* d_in, const int* in_sizes, int n_in,
                              void* d_out, int out_size) {
    const float* x      = (const float*)d_in[0];
    const float* wgates = (const float*)d_in[1];
    const float* bgates = (const float*)d_in[2];
    const float* W1     = (const float*)d_in[3];
    const float* b1     = (const float*)d_in[4];
    const float* W2     = (const float*)d_in[5];
    const float* b2     = (const float*)d_in[6];
    const float* W3     = (const float*)d_in[7];
    const float* b3     = (const float*)d_in[8];
    float* out = (float*)d_out;

    cudaFuncSetAttribute(moe_mma, cudaFuncAttributeMaxDynamicSharedMemorySize, SMEM_BYTES);

    moe_prep<<<(NCHUNK * 304 * KC + 255) / 256, 256>>>(W1, wgates);
    moe_mma<<<BN / MROWS, NTH, SMEM_BYTES>>>(x, bgates, b1, W2, b2, W3, b3, out);
    moe_finalize_kernel<<<1, 32>>>(out, out_size);
}

// round 17
// speedup vs baseline: 5.2629x; 1.0062x over previous
#include <cuda_runtime.h>
#include <cuda_bf16.h>
#include <cuda_fp16.h>
#include <stdint.h>
#include <math.h>

#define BN 32768
#define DN 512
#define EN 16
#define TT 3
#define ON 16
#define MROWS 128
#define NTH 512
#define NCHUNK 16
#define KC 32
#define CHB 28160           // B chunk bytes: 256*80 (fp16 h1) + 2*48*80 (fp16 gates)
#define GOFF 20480          // gate region offset inside B chunk
#define ATERM 10240         // A per-term bytes (128 rows * 80)
#define ABUF 20480          // A per-buffer: 2 fp16 terms
#define BBASE 40960         // B region start (after 2 A buffers)
// float offsets (epilogue layout identical to R14)
#define H1_F 0              // 128*273
#define LG_F 34944          // 128*49
#define B1T 41216
#define BGT 41472
#define W2T 41520
#define W3T 43600
#define B2T 45680
#define B3T 45824
#define IMPT 46096
#define LDT 46144
#define LSET 46192
// byte offsets
#define MBAR0_B 185280
#define MBAR1_B 185288
#define SMEM_BYTES 185344

__device__ __align__(16) unsigned char g_wimg[NCHUNK * CHB];
__device__ float g_imp[TT * EN];
__device__ float g_load[TT * EN];
__device__ float g_rz;

__device__ __forceinline__ uint32_t smem_u32(const void* p) {
    uint32_t a;
    asm("{ .reg .u64 t; cvta.to.shared.u64 t, %1; cvt.u32.u64 %0, t; }" : "=r"(a) : "l"(p));
    return a;
}
__device__ __forceinline__ void ldsm4(uint32_t* r, uint32_t a) {
    asm volatile("ldmatrix.sync.aligned.m8n8.x4.shared.b16 {%0,%1,%2,%3}, [%4];"
                 : "=r"(r[0]), "=r"(r[1]), "=r"(r[2]), "=r"(r[3]) : "r"(a));
}
__device__ __forceinline__ void ldsm2(uint32_t* r, uint32_t a) {
    asm volatile("ldmatrix.sync.aligned.m8n8.x2.shared.b16 {%0,%1}, [%2];"
                 : "=r"(r[0]), "=r"(r[1]) : "r"(a));
}
__device__ __forceinline__ void mmah(float* c, const uint32_t* a, const uint32_t* b) {
    asm volatile("mma.sync.aligned.m16n8k16.row.col.f32.f16.f16.f32 "
                 "{%0,%1,%2,%3},{%4,%5,%6,%7},{%8,%9},{%0,%1,%2,%3};"
                 : "+f"(c[0]), "+f"(c[1]), "+f"(c[2]), "+f"(c[3])
                 : "r"(a[0]), "r"(a[1]), "r"(a[2]), "r"(a[3]), "r"(b[0]), "r"(b[1]));
}
#define MBARRIER_INIT(mb, n) \
    asm volatile("mbarrier.init.shared.b64 [%0], %1;" :: "r"((uint32_t)(mb)), "r"((uint32_t)(n)) : "memory")
#define MBARRIER_EXPECT_TX(mb, tx) \
    asm volatile("mbarrier.arrive.expect_tx.shared.b64 _, [%0], %1;" \
                 :: "r"((uint32_t)(mb)), "r"((uint32_t)(tx)) : "memory")
#define BULK_G2S(dst, src, bytes, mb) \
    asm volatile("cp.async.bulk.shared::cluster.global.mbarrier::complete_tx::bytes [%0], [%1], %2, [%3];" \
                 :: "r"((uint32_t)(dst)), "l"(src), "r"((uint32_t)(bytes)), "r"((uint32_t)(mb)) : "memory")
#define MBARRIER_WAIT_PARITY(mb, par) do {                                          \
    uint32_t _mb = (uint32_t)(mb), _p = (uint32_t)(par), _done;                     \
    asm volatile("{\n\t.reg .pred p;\n\t"                                           \
        "mbarrier.try_wait.parity.acquire.cta.shared::cta.b64 p, [%1], %2;\n\t"     \
        "selp.b32 %0, 1, 0, p;\n\t}" : "=r"(_done) : "r"(_mb), "r"(_p) : "memory"); \
    if (!_done) {                                                                   \
        asm volatile("{\n\t.reg .pred P1;\n\t"                                      \
            "WL_%=:\n\t"                                                            \
            "mbarrier.try_wait.parity.acquire.cta.shared::cta.b64 P1, [%0], %1, 0x989680;\n\t" \
            "@P1 bra.uni WD_%=;\n\t"                                                \
            "bra.uni WL_%=;\n\t"                                                    \
            "WD_%=:\n\t}" :: "r"(_mb), "r"(_p) : "memory");                         \
    }                                                                               \
} while (0)

// ---------- prepass: h1 weights -> fp16 single; gate weights -> fp16 2-term split ----------
__global__ void moe_prep(const float* __restrict__ W1, const float* __restrict__ wg) {
    if (blockIdx.x == 0) {
        int i = threadIdx.x;
        if (i < TT * EN) { g_imp[i] = 0.f; g_load[i] = 0.f; }
        if (i == 0) g_rz = 0.f;
    }
    int idx = blockIdx.x * blockDim.x + threadIdx.x;
    if (idx >= NCHUNK * 304 * KC) return;
    int c = idx / (304 * KC);
    int r = idx - c * (304 * KC);
    int n = r >> 5, k = r & 31, d = c * KC + k;
    unsigned char* base = g_wimg + (size_t)c * CHB;
    if (n < 256) {
        float w = W1[(n >> 4) * (DN * 16) + d * 16 + (n & 15)];
        *(__half*)(base + n * 80 + 2 * k) = __float2half_rn(w);
    } else {
        int gn = n - 256;
        float w = wg[(gn >> 4) * (DN * EN) + d * 16 + (gn & 15)];
        __half t0 = __float2half_rn(w);
        __half t1 = __float2half_rn(w - __half2float(t0));
        *(__half*)(base + GOFF + gn * 80 + 2 * k) = t0;
        *(__half*)(base + GOFF + 3840 + gn * 80 + 2 * k) = t1;
    }
}

// ---------- main ----------
extern __shared__ float sm[];

__global__ __launch_bounds__(NTH, 1)
void moe_mma(const float* __restrict__ x,
             const float* __restrict__ bgates,
             const float* __restrict__ b1,
             const float* __restrict__ W2,
             const float* __restrict__ b2,
             const float* __restrict__ W3,
             const float* __restrict__ b3,
             float* __restrict__ out) {
    const int tid = threadIdx.x;
    const int wid = tid >> 5, l = tid & 31;
    const int mrow = wid & 3, ncol = wid >> 2;
    const int row0 = blockIdx.x * MROWS;
    const uint32_t sb = smem_u32(sm);
    const uint32_t mb0 = sb + MBAR0_B, mb1 = sb + MBAR1_B;

    for (int i = tid; i < 256; i += NTH) sm[B1T + i] = b1[i];
    if (tid < 48) { sm[BGT + tid] = bgates[tid]; sm[IMPT + tid] = 0.f; sm[LDT + tid] = 0.f; }
    for (int i = tid; i < 2048; i += NTH) {
        sm[W2T + (i >> 7) * 130 + (i & 127)] = W2[i];
        sm[W3T + (i >> 7) * 130 + (i & 127)] = W3[i];
    }
    for (int i = tid; i < 128; i += NTH) sm[B2T + (i >> 3) * 9 + (i & 7)] = b2[i];
    for (int i = tid; i < 256; i += NTH) sm[B3T + (i >> 4) * 17 + (i & 15)] = b3[i];

    if (tid == 0) { MBARRIER_INIT(mb0, 1); MBARRIER_INIT(mb1, 1); }
    __syncthreads();
    if (tid == 0) {
        MBARRIER_EXPECT_TX(mb0, CHB);
        BULK_G2S(sb + BBASE, g_wimg, CHB, mb0);
    }

    float c[2][10][4];
#pragma unroll
    for (int i = 0; i < 2; i++)
#pragma unroll
        for (int j = 0; j < 10; j++)
#pragma unroll
            for (int q = 0; q < 4; q++) c[i][j][q] = 0.f;

    const uint32_t aoff = (uint32_t)((mrow * 32 + ((l >> 3) & 1) * 8 + (l & 7)) * 80 + (l >> 4) * 16);
    const uint32_t boff = (uint32_t)((l & 7) * 80 + ((l >> 3) & 1) * 16);
    const uint32_t boff4 = boff + (uint32_t)(l >> 4) * 640;   // x4: lanes 16-31 -> next n-tile
    const int srow = tid >> 2, skq = tid & 3;
    const float* xp = x + (size_t)(row0 + srow) * DN + skq * 8;
    const uint32_t stoff = (uint32_t)(srow * 80 + skq * 16);
    float lm = -INFINITY, ls = 0.f;
    float4 xa, xb;

#define STAGE_A(bq) do {                                                       \
    float v_[8] = {xa.x, xa.y, xa.z, xa.w, xb.x, xb.y, xb.z, xb.w};            \
    float cm_ = v_[0];                                                         \
    _Pragma("unroll") for (int i_ = 1; i_ < 8; i_++) cm_ = fmaxf(cm_, v_[i_]); \
    float nm_ = fmaxf(lm, cm_);                                                \
    ls *= __expf(lm - nm_);                                                    \
    float ad_ = 0.f;                                                           \
    _Pragma("unroll") for (int i_ = 0; i_ < 8; i_++) ad_ += __expf(v_[i_] - nm_); \
    ls += ad_; lm = nm_;                                                       \
    uint32_t r0_[4], r1_[4];                                                   \
    _Pragma("unroll") for (int i_ = 0; i_ < 4; i_++) {                         \
        __half h0_ = __float2half_rn(v_[2 * i_]);                              \
        __half h1_ = __float2half_rn(v_[2 * i_ + 1]);                          \
        r0_[i_] = ((uint32_t)__half_as_ushort(h1_) << 16) |                    \
                  (uint32_t)__half_as_ushort(h0_);                             \
        __half d0_ = __float2half_rn(v_[2 * i_] - __half2float(h0_));          \
        __half d1_ = __float2half_rn(v_[2 * i_ + 1] - __half2float(h1_));      \
        r1_[i_] = ((uint32_t)__half_as_ushort(d1_) << 16) |                    \
                  (uint32_t)__half_as_ushort(d0_);                             \
    }                                                                          \
    asm volatile("st.shared.v4.b32 [%0], {%1,%2,%3,%4};"                       \
        :: "r"(sb + (bq) * ABUF + stoff),                                      \
           "r"(r0_[0]), "r"(r0_[1]), "r"(r0_[2]), "r"(r0_[3]) : "memory");     \
    asm volatile("st.shared.v4.b32 [%0], {%1,%2,%3,%4};"                       \
        :: "r"(sb + (bq) * ABUF + ATERM + stoff),                              \
           "r"(r1_[0]), "r"(r1_[1]), "r"(r1_[2]), "r"(r1_[3]) : "memory");     \
    } while (0)

    xa = *(const float4*)xp;
    xb = *(const float4*)(xp + 4);
    STAGE_A(0);

    for (int ch = 0; ch < NCHUNK; ++ch) {
        int buf = ch & 1;
        if (ch < NCHUNK - 1) {
            const float* xq = xp + (ch + 1) * KC;
            xa = *(const float4*)xq;
            xb = *(const float4*)(xq + 4);
        }
        MBARRIER_WAIT_PARITY(buf ? mb1 : mb0, (ch >> 1) & 1);
        __syncthreads();
        if (ch < NCHUNK - 1 && tid == 0) {
            uint32_t mbn = (buf ^ 1) ? mb1 : mb0;
            MBARRIER_EXPECT_TX(mbn, CHB);
            BULK_G2S(sb + BBASE + (buf ^ 1) * CHB,
                     g_wimg + (size_t)(ch + 1) * CHB, CHB, mbn);
        }

        {
            uint32_t Ab = sb + buf * ABUF;
            uint32_t Bb = sb + BBASE + buf * CHB;
            if (ncol < 3) {
                // h1 tiles: single fp16 term, paired-n ldsm4 B loads
#pragma unroll
                for (int ks = 0; ks < 2; ++ks) {
                    uint32_t a[2][4];
#pragma unroll
                    for (int mt = 0; mt < 2; mt++)
                        ldsm4(a[mt], Ab + aoff + mt * 1280 + ks * 32);
#pragma unroll
                    for (int np = 0; np < 5; ++np) {
                        uint32_t b[4];
                        ldsm4(b, Bb + (uint32_t)((ncol * 80 + np * 16) * 80) + boff4 + ks * 32);
#pragma unroll
                        for (int mt = 0; mt < 2; mt++) {
                            mmah(c[mt][2 * np], a[mt], b);
                            mmah(c[mt][2 * np + 1], a[mt], b + 2);
                        }
                    }
                }
            } else {
#pragma unroll
                for (int ks = 0; ks < 2; ++ks) {
                    uint32_t a0[2][4], a1[2][4];
#pragma unroll
                    for (int mt = 0; mt < 2; mt++) {
                        ldsm4(a0[mt], Ab + aoff + mt * 1280 + ks * 32);
                        ldsm4(a1[mt], Ab + ATERM + aoff + mt * 1280 + ks * 32);
                    }
                    // leftover h1 cols 240-255 (fp16 term0)
#pragma unroll
                    for (int nt = 0; nt < 2; ++nt) {
                        uint32_t b[2];
                        ldsm2(b, Bb + (uint32_t)((240 + nt * 8) * 80) + boff + ks * 32);
#pragma unroll
                        for (int mt = 0; mt < 2; mt++) mmah(c[mt][nt], a0[mt], b);
                    }
                    // gates: fp16 2-term split, 3 combos
#pragma unroll
                    for (int nt = 0; nt < 6; ++nt) {
                        uint32_t b0[2], b1[2];
                        uint32_t ba = Bb + GOFF + (uint32_t)(nt * 8 * 80) + boff + ks * 32;
                        ldsm2(b0, ba);
                        ldsm2(b1, ba + 3840);
#pragma unroll
                        for (int mt = 0; mt < 2; mt++) {
                            float* cc = c[mt][2 + nt];
                            mmah(cc, a0[mt], b0);
                            mmah(cc, a0[mt], b1);
                            mmah(cc, a1[mt], b0);
                        }
                    }
                }
            }
        }
        if (ch < NCHUNK - 1) STAGE_A(buf ^ 1);
    }
    __syncthreads();

    // ---- C writeback: bias + relu into padded epilogue smem ----
    {
        int r4 = l >> 2, c2 = 2 * (l & 3);
        if (ncol < 3) {
#pragma unroll
            for (int mt = 0; mt < 2; mt++)
#pragma unroll
                for (int nt = 0; nt < 10; nt++) {
                    int col = ncol * 80 + nt * 8 + c2;
                    int e = col >> 4, h = col & 15;
#pragma unroll
                    for (int hh = 0; hh < 2; hh++) {
                        int row = mrow * 32 + mt * 16 + hh * 8 + r4;
                        sm[H1_F + row * 273 + e * 17 + h] =
                            fmaxf(c[mt][nt][hh * 2] + sm[B1T + col], 0.f);
                        sm[H1_F + row * 273 + e * 17 + h + 1] =
                            fmaxf(c[mt][nt][hh * 2 + 1] + sm[B1T + col + 1], 0.f);
                    }
                }
        } else {
#pragma unroll
            for (int mt = 0; mt < 2; mt++) {
#pragma unroll
                for (int nt = 0; nt < 2; nt++) {
                    int col = 240 + nt * 8 + c2;
                    int e = col >> 4, h = col & 15;
#pragma unroll
                    for (int hh = 0; hh < 2; hh++) {
                        int row = mrow * 32 + mt * 16 + hh * 8 + r4;
                        sm[H1_F + row * 273 + e * 17 + h] =
                            fmaxf(c[mt][nt][hh * 2] + sm[B1T + col], 0.f);
                        sm[H1_F + row * 273 + e * 17 + h + 1] =
                            fmaxf(c[mt][nt][hh * 2 + 1] + sm[B1T + col + 1], 0.f);
                    }
                }
#pragma unroll
                for (int nt = 0; nt < 6; nt++) {
                    int gc = nt * 8 + c2;
#pragma unroll
                    for (int hh = 0; hh < 2; hh++) {
                        int row = mrow * 32 + mt * 16 + hh * 8 + r4;
                        sm[LG_F + row * 49 + gc] = c[mt][2 + nt][hh * 2] + sm[BGT + gc];
                        sm[LG_F + row * 49 + gc + 1] = c[mt][2 + nt][hh * 2 + 1] + sm[BGT + gc + 1];
                    }
                }
            }
        }
    }
    // ---- LSE merge (4 threads per row) ----
#pragma unroll
    for (int o = 1; o < 4; o <<= 1) {
        float m2 = __shfl_xor_sync(0xffffffffu, lm, o);
        float s2 = __shfl_xor_sync(0xffffffffu, ls, o);
        float nm = fmaxf(lm, m2);
        ls = ls * __expf(lm - nm) + s2 * __expf(m2 - nm);
        lm = nm;
    }
    if (skq == 0) sm[LSET + srow] = lm + __logf(ls);
    __syncthreads();

    if (tid == 0) {
        float s = 0.f;
        for (int r = 0; r < MROWS; r++) s += sm[LSET + r];
        atomicAdd(&g_rz, s);
    }

    // ---- gating + expert layers 2/3 ----
    if (tid < MROWS * TT) {
        int t = tid / MROWS;
        int row = tid - t * MROWS;
        float lg[16];
#pragma unroll
        for (int e = 0; e < 16; e++) lg[e] = sm[LG_F + row * 49 + t * 16 + e];
        int sel[4];
        float sv[4];
#pragma unroll
        for (int k = 0; k < 4; k++) {
            float best = -INFINITY;
            int bi = 0;
#pragma unroll
            for (int e = 0; e < 16; e++)
                if (lg[e] > best) { best = lg[e]; bi = e; }
            sv[k] = best; sel[k] = bi; lg[bi] = -INFINITY;
        }
        float m = sv[0], g4[4], ssum = 0.f;
#pragma unroll
        for (int k = 0; k < 4; k++) { g4[k] = __expf(sv[k] - m); ssum += g4[k]; }
        float inv = 1.f / ssum;
        float y[16];
#pragma unroll
        for (int o = 0; o < 16; o++) y[o] = 0.f;
#pragma unroll
        for (int k = 0; k < 4; k++) {
            int e = sel[k];
            float gk = g4[k] * inv;
            float h[16];
#pragma unroll
            for (int i = 0; i < 16; i++) h[i] = sm[H1_F + row * 273 + e * 17 + i];
            float h2v[8];
#pragma unroll
            for (int j = 0; j < 8; j++) {
                float a = sm[B2T + e * 9 + j];
#pragma unroll
                for (int i = 0; i < 16; i++) a += h[i] * sm[W2T + e * 130 + i * 8 + j];
                h2v[j] = fmaxf(a, 0.f);
            }
#pragma unroll
            for (int o = 0; o < 16; o++) {
                float a = sm[B3T + e * 17 + o];
#pragma unroll
                for (int j = 0; j < 8; j++) a += h2v[j] * sm[W3T + e * 130 + j * 16 + o];
                y[o] += gk * fmaxf(a, 0.f);
            }
            atomicAdd(&sm[IMPT + t * 16 + e], gk);
            atomicAdd(&sm[LDT + t * 16 + e], 1.f);
        }
        float* yo = out + (size_t)t * BN * ON + (size_t)(row0 + row) * ON;
#pragma unroll
        for (int o = 0; o < 16; o++) yo[o] = y[o];
    }
    __syncthreads();
    if (tid < 48) atomicAdd(&g_imp[tid], sm[IMPT + tid]);
    else if (tid < 96) atomicAdd(&g_load[tid - 48], sm[LDT + tid - 48]);
}

__global__ void moe_finalize_kernel(float* __restrict__ out, int out_size) {
    if (threadIdx.x != 0 || blockIdx.x != 0) return;
    float lb = 0.f;
    for (int t = 0; t < TT; t++) {
        float imp[16], ld[16];
        float si = 0.f, sl = 0.f, sil = 0.f;
        for (int e = 0; e < 16; e++) {
            imp[e] = g_imp[t * 16 + e];
            ld[e]  = g_load[t * 16 + e];
            si += imp[e]; sl += ld[e]; sil += imp[e] * ld[e];
        }
        float mi = si / 16.f, ml = sl / 16.f;
        float vi = 0.f, vl = 0.f;
        for (int e = 0; e < 16; e++) {
            float di = imp[e] - mi, dl = ld[e] - ml;
            vi += di * di; vl += dl * dl;
        }
        vi /= 15.f; vl /= 15.f;
        lb += 0.01f * (vi / (mi * mi + 1e-10f) + vl / (ml * ml + 1e-10f))
            + 0.01f * 16.f * sil / (float)BN;
    }
    size_t base = (size_t)TT * BN * ON;
    if (out_size > (int)base)     out[base]     = lb;
    if (out_size > (int)base + 1) out[base + 1] = 3.f * 0.001f * g_rz / (float)BN;
}

extern "C" void kernel_launch(void* const* d_in, const int* in_sizes, int n_in,
                              void* d_out, int out_size) {
    const float* x      = (const float*)d_in[0];
    const float* wgates = (const float*)d_in[1];
    const float* bgates = (const float*)d_in[2];
    const float* W1     = (const float*)d_in[3];
    const float* b1     = (const float*)d_in[4];
    const float* W2     = (const float*)d_in[5];
    const float* b2     = (const float*)d_in[6];
    const float* W3     = (const float*)d_in[7];
    const float* b3     = (const float*)d_in[8];
    float* out = (float*)d_out;

    cudaFuncSetAttribute(moe_mma, cudaFuncAttributeMaxDynamicSharedMemorySize, SMEM_BYTES);

    moe_prep<<<(NCHUNK * 304 * KC + 255) / 256, 256>>>(W1, wgates);
    moe_mma<<<BN / MROWS, NTH, SMEM_BYTES>>>(x, bgates, b1, W2, b2, W3, b3, out);
    moe_finalize_kernel<<<1, 32>>>(out, out_size);
}